// round 10
// baseline (speedup 1.0000x reference)
#include <cuda_runtime.h>
#include <cstdint>

// ---------------- problem constants ----------------
#define NN 100000
#define VV 3
#define EE 500000
#define VN (VV * NN)
#define EPSL 1e-5f

#define BN 128         // nodes per tile
#define NT 512         // 16 warps; warp = 8-node row group
#define NTILES ((NN + BN - 1) / BN)   // 782

typedef unsigned long long ull;

// ---------------- scratch (device globals; no allocation) ----------------
__device__ float g_pre[(size_t)VV * NN * 128];
__device__ float g_wsum[VN];
__device__ float g_transformed[(size_t)NN * 128];
__device__ float g_nodeatt[NN];
__device__ float g_viewout[(size_t)VV * NN * 128];
__device__ float g_vscore[VN];
__device__ float g_W01[128 * 128];    // selfW @ fusW[0:128]
__device__ float g_b01[128];          // fusb + selfb @ fusW[0:128]
// CSR build
__device__ int   g_cnt[VN];
__device__ int   g_rowstart[VN + 1];
__device__ int   g_cursor[VN];
__device__ int   g_esrc_s[VV * EE];
__device__ float g_ew_s[VV * EE];

// ---------------- small helpers ----------------
__device__ __forceinline__ void ffma2(ull &d, ull a, ull b) {
    asm("fma.rn.f32x2 %0, %1, %2, %0;" : "+l"(d) : "l"(a), "l"(b));
}
__device__ __forceinline__ ull fdup(float a) {
    ull r; asm("mov.b64 %0, {%1, %1};" : "=l"(r) : "f"(a)); return r;
}
__device__ __forceinline__ float2 u2f(ull v) {
    float2 r; asm("mov.b64 {%0, %1}, %2;" : "=f"(r.x), "=f"(r.y) : "l"(v)); return r;
}
__device__ __forceinline__ float sigm(float x) { return 1.f / (1.f + __expf(-x)); }

__device__ __forceinline__ unsigned smaddr(const void* p) {
    unsigned r;
    asm("{ .reg .u64 t; cvta.to.shared.u64 t, %1; cvt.u32.u64 %0, t; }" : "=r"(r) : "l"(p));
    return r;
}
#define MBAR_INIT(a) asm volatile("mbarrier.init.shared.b64 [%0], 1;" :: "r"(a))
#define MBAR_EXPECT(a, bytes) \
    asm volatile("mbarrier.arrive.expect_tx.shared.b64 _, [%0], %1;" :: "r"(a), "r"(bytes))
#define MBAR_WAIT(a, parity) do { \
    unsigned _p = 0; \
    while (!_p) { \
        asm volatile("{\n\t.reg .pred P;\n\t" \
                     "mbarrier.try_wait.parity.shared.b64 P, [%1], %2, 0x989680;\n\t" \
                     "selp.u32 %0, 1, 0, P;\n\t}" \
                     : "=r"(_p) : "r"(a), "r"((unsigned)(parity))); \
    } } while (0)

__device__ __forceinline__ void bulk_g2s(unsigned dst, const void* src, unsigned bytes, unsigned mbar) {
    asm volatile("cp.async.bulk.shared::cluster.global.mbarrier::complete_tx::bytes [%0], [%1], %2, [%3];"
                 :: "r"(dst), "l"(src), "r"(bytes), "r"(mbar) : "memory");
}

__device__ __forceinline__ float wred32(float x) {
#pragma unroll
    for (int off = 16; off > 0; off >>= 1)
        x += __shfl_xor_sync(0xffffffffu, x, off);
    return x;
}
__device__ __forceinline__ float wred16(float x) {
#pragma unroll
    for (int off = 8; off > 0; off >>= 1)
        x += __shfl_xor_sync(0xffffffffu, x, off);
    return x;
}

// ---------------- CSR build kernels ----------------
__global__ void k_zc() {
    int i = blockIdx.x * blockDim.x + threadIdx.x;
    int stride = gridDim.x * blockDim.x;
    for (; i < VN; i += stride) g_cnt[i] = 0;
}

__global__ void k_cnt(const int* __restrict__ dst) {
    int i = blockIdx.x * blockDim.x + threadIdx.x;
    int stride = gridDim.x * blockDim.x;
    for (; i < VV * EE; i += stride) {
        int v = i / EE;
        atomicAdd(&g_cnt[v * NN + __ldg(dst + i)], 1);
    }
}

__global__ void __launch_bounds__(1024) k_scan() {
    __shared__ int part[1024];
    int t = threadIdx.x;
    const int CH = (VN + 1023) / 1024;   // 293
    int base = t * CH;
    int sum = 0;
    for (int i = 0; i < CH; ++i) {
        int idx = base + i;
        if (idx < VN) sum += g_cnt[idx];
    }
    part[t] = sum;
    __syncthreads();
    for (int off = 1; off < 1024; off <<= 1) {
        int v = (t >= off) ? part[t - off] : 0;
        __syncthreads();
        part[t] += v;
        __syncthreads();
    }
    int run = part[t] - sum;   // exclusive prefix of this chunk
    for (int i = 0; i < CH; ++i) {
        int idx = base + i;
        if (idx < VN) {
            g_rowstart[idx] = run;
            g_cursor[idx] = run;
            run += g_cnt[idx];
        }
    }
    if (t == 1023) g_rowstart[VN] = run;
}

__global__ void k_scatter(const int* __restrict__ src, const int* __restrict__ dst,
                          const float* __restrict__ w) {
    int i = blockIdx.x * blockDim.x + threadIdx.x;
    int stride = gridDim.x * blockDim.x;
    for (; i < VV * EE; i += stride) {
        int v = i / EE;
        int key = v * NN + __ldg(dst + i);
        int pos = atomicAdd(&g_cursor[key], 1);
        g_esrc_s[pos] = __ldg(src + i);
        g_ew_s[pos] = __ldg(w + i);
    }
}

// one warp per (view,node); edges processed in chunks of 8 for MLP
__global__ void __launch_bounds__(256) k_gather(const float* __restrict__ feats) {
    int wid = (int)(((size_t)blockIdx.x * 256 + threadIdx.x) >> 5);
    if (wid >= VN) return;
    int lane = threadIdx.x & 31;
    int p = __ldg(g_rowstart + wid);
    int end = __ldg(g_rowstart + wid + 1);
    float4 acc = make_float4(0.f, 0.f, 0.f, 0.f);
    float wsum = 0.f;
    while (p < end) {
        int m = end - p;
        if (m > 8) m = 8;
        int s[8];
        float we[8];
#pragma unroll
        for (int j = 0; j < 8; ++j) {
            s[j] = (j < m) ? __ldg(g_esrc_s + p + j) : 0;
            we[j] = (j < m) ? __ldg(g_ew_s + p + j) : 0.f;
        }
        float4 x[8];
#pragma unroll
        for (int j = 0; j < 8; ++j) {
            if (j < m)
                x[j] = __ldg(reinterpret_cast<const float4*>(feats + (size_t)s[j] * 128) + lane);
            else
                x[j] = make_float4(0.f, 0.f, 0.f, 0.f);
        }
#pragma unroll
        for (int j = 0; j < 8; ++j) {
            acc.x = fmaf(we[j], x[j].x, acc.x);
            acc.y = fmaf(we[j], x[j].y, acc.y);
            acc.z = fmaf(we[j], x[j].z, acc.z);
            acc.w = fmaf(we[j], x[j].w, acc.w);
            wsum += we[j];
        }
        p += 8;
    }
    reinterpret_cast<float4*>(g_pre + (size_t)wid * 128)[lane] = acc;
    if (lane == 0) g_wsum[wid] = wsum;
}

// ---------------- precompute W01 = selfW @ fusW[0:128), b01 = fusb + selfb @ fusW1 ----------------
__global__ void k_pre(const float* __restrict__ selfW, const float* __restrict__ selfb,
                      const float* __restrict__ fusW, const float* __restrict__ fusb) {
    int c = threadIdx.x;
    int i = blockIdx.x;
    float s = 0.f;
#pragma unroll 8
    for (int m = 0; m < 128; ++m)
        s = fmaf(selfW[i * 128 + m], __ldg(fusW + m * 128 + c), s);
    g_W01[i * 128 + c] = s;
    if (i == 0) {
        float b = __ldg(fusb + c);
#pragma unroll 8
        for (int m = 0; m < 128; ++m)
            b = fmaf(__ldg(selfb + m), __ldg(fusW + m * 128 + c), b);
        g_b01[c] = b;
    }
}

// ---------------- warp-private tile loader ----------------
__device__ __forceinline__ void load_rows_warp(const float* __restrict__ g, int nb, int n0,
                                               int lane, float* __restrict__ Fs) {
#pragma unroll
    for (int i = 0; i < 8; ++i) {
        int n = nb + n0 + i;
        float4 v = make_float4(0.f, 0.f, 0.f, 0.f);
        if (n < NN) v = reinterpret_cast<const float4*>(g + (size_t)n * 128)[lane];
        reinterpret_cast<float4*>(Fs + (n0 + i) * 128)[lane] = v;
    }
}

// ---------------- 8x4 register-blocked matmul, FFMA2, broadcast A ----------------
template <int BSTRIDE>
__device__ __forceinline__ void mm8x4(const float* __restrict__ Fs, const float* __restrict__ wbase,
                                      ull acc2[8][2], int n0) {
#pragma unroll 2
    for (int kk = 0; kk < 128; kk += 4) {
        float4 a4[8];
#pragma unroll
        for (int i = 0; i < 8; ++i)
            a4[i] = *reinterpret_cast<const float4*>(Fs + (n0 + i) * 128 + kk);
#pragma unroll
        for (int q = 0; q < 4; ++q) {
            ulonglong2 b = *reinterpret_cast<const ulonglong2*>(wbase + (kk + q) * BSTRIDE);
#pragma unroll
            for (int i = 0; i < 8; ++i) {
                float av = (q == 0) ? a4[i].x : (q == 1) ? a4[i].y : (q == 2) ? a4[i].z : a4[i].w;
                ull ad = fdup(av);
                ffma2(acc2[i][0], ad, b.x);
                ffma2(acc2[i][1], ad, b.y);
            }
        }
    }
}

__device__ __forceinline__ void mm8x2_64(const float* __restrict__ Fs, const float* __restrict__ wbase,
                                         ull acc[8], int n0) {
#pragma unroll 2
    for (int kk = 0; kk < 128; kk += 4) {
        float4 a4[8];
#pragma unroll
        for (int i = 0; i < 8; ++i)
            a4[i] = *reinterpret_cast<const float4*>(Fs + (n0 + i) * 128 + kk);
#pragma unroll
        for (int q = 0; q < 4; ++q) {
            ull b = *reinterpret_cast<const ull*>(wbase + (kk + q) * 64);
#pragma unroll
            for (int i = 0; i < 8; ++i) {
                float av = (q == 0) ? a4[i].x : (q == 1) ? a4[i].y : (q == 2) ? a4[i].z : a4[i].w;
                ffma2(acc[i], fdup(av), b);
            }
        }
    }
}

#define ZERO_ACC(acc2) do { \
    _Pragma("unroll") for (int i = 0; i < 8; ++i) { acc2[i][0] = 0ull; acc2[i][1] = 0ull; } } while (0)

// ---------------- feature-side kernel (warp-synchronous after init) ----------------
__global__ void __launch_bounds__(NT, 1) k_feat(
    const float* __restrict__ feats,
    const float* __restrict__ clsW, const float* __restrict__ clsb,
    const float* __restrict__ attW1, const float* __restrict__ attb1,
    const float* __restrict__ attW2, const float* __restrict__ attb2,
    const float* __restrict__ attbias,
    const float* __restrict__ featW, const float* __restrict__ featb,
    float* __restrict__ out_cp) {
    extern __shared__ float sm[];
    float* Fs = sm + 8;
    float* W0 = Fs + 16384;
    float* W1 = W0 + 16384;
    unsigned mb0 = smaddr(sm), mb1 = mb0 + 8;

    int nb = blockIdx.x * BN;
    int t = threadIdx.x;
    int lane = t & 31;
    int ng = t >> 5;
    int n0 = ng * 8, c0 = lane * 4;

    if (t == 0) { MBAR_INIT(mb0); MBAR_INIT(mb1); }
    __syncthreads();
    if (t == 0) {
        MBAR_EXPECT(mb0, 65536u);
        bulk_g2s(smaddr(W0), featW, 65536u, mb0);
        MBAR_EXPECT(mb1, 65536u);
        bulk_g2s(smaddr(W1), attW1, 65536u, mb1);
    }
    load_rows_warp(feats, nb, n0, lane, Fs);
    __syncwarp();

    ull acc2[8][2];

    // ---- transformed = f @ featW + featb ----
    MBAR_WAIT(mb0, 0);
    ZERO_ACC(acc2);
    mm8x4<128>(Fs, W0 + c0, acc2, n0);
    {
        float4 b0 = __ldg(reinterpret_cast<const float4*>(featb + c0));
#pragma unroll
        for (int i = 0; i < 8; ++i) {
            int n = nb + n0 + i;
            if (n < NN) {
                float2 p0 = u2f(acc2[i][0]), p1 = u2f(acc2[i][1]);
                *reinterpret_cast<float4*>(g_transformed + (size_t)n * 128 + c0) =
                    make_float4(p0.x + b0.x, p0.y + b0.y, p1.x + b0.z, p1.y + b0.w);
            }
        }
    }

    // ---- label attention ----
    float sc[8], sco[8];
    MBAR_WAIT(mb1, 0);
    ZERO_ACC(acc2);
    {
        int cls = c0 >> 6;
        mm8x4<64>(Fs, W1 + cls * 8192 + (c0 & 63), acc2, n0);
        float4 ab = __ldg(reinterpret_cast<const float4*>(attb1 + c0));
        float4 aw = __ldg(reinterpret_cast<const float4*>(attW2 + c0));
        float b2v = __ldg(attb2 + cls);
#pragma unroll
        for (int i = 0; i < 8; ++i) {
            float2 f0 = u2f(acc2[i][0]), f1 = u2f(acc2[i][1]);
            float p = fmaxf(f0.x + ab.x, 0.f) * aw.x
                    + fmaxf(f0.y + ab.y, 0.f) * aw.y
                    + fmaxf(f1.x + ab.z, 0.f) * aw.z
                    + fmaxf(f1.y + ab.w, 0.f) * aw.w;
            p = wred16(p);
            sc[i] = sigm(p + b2v);
            sco[i] = __shfl_xor_sync(0xffffffffu, sc[i], 16);
        }
    }

    // ---- class probs + node_att ----
    {
        float4 cw0 = __ldg(reinterpret_cast<const float4*>(clsW + c0 * 2));
        float4 cw1 = __ldg(reinterpret_cast<const float4*>(clsW + c0 * 2) + 1);
        float cb0 = __ldg(clsb), cb1 = __ldg(clsb + 1), abv = __ldg(attbias);
#pragma unroll
        for (int i = 0; i < 8; ++i) {
            float4 f = *reinterpret_cast<const float4*>(Fs + (n0 + i) * 128 + c0);
            float p0 = f.x * cw0.x + f.y * cw0.z + f.z * cw1.x + f.w * cw1.z;
            float p1 = f.x * cw0.y + f.y * cw0.w + f.z * cw1.y + f.w * cw1.w;
            p0 = wred32(p0);
            p1 = wred32(p1);
            int n = nb + n0 + i;
            if (lane == 0 && n < NN) {
                float l0 = p0 + cb0, l1 = p1 + cb1;
                float m = fmaxf(l0, l1);
                float e0 = __expf(l0 - m), e1 = __expf(l1 - m);
                float inv = 1.f / (e0 + e1);
                float cp0 = e0 * inv, cp1 = e1 * inv;
                out_cp[(size_t)n * 2] = cp0;
                out_cp[(size_t)n * 2 + 1] = cp1;
                g_nodeatt[n] = sc[i] * cp0 + sco[i] * cp1 + abv;
            }
        }
    }
}

// ---------------- per-view kernel (warp-synchronous after init) ----------------
__global__ void __launch_bounds__(NT, 1) k_view(
    const float* __restrict__ relW, const float* __restrict__ relb,
    const float* __restrict__ gateW, const float* __restrict__ gateb,
    const float* __restrict__ view_pref,
    const float* __restrict__ vattW1, const float* __restrict__ vattb1,
    const float* __restrict__ vattW2, const float* __restrict__ vattb2) {
    extern __shared__ float sm[];
    float* Fs = sm + 8;
    float* W0 = Fs + 16384;
    float* W1 = W0 + 16384;
    float* W2 = W1 + 16384;
    unsigned mb0 = smaddr(sm), mb1 = mb0 + 8, mb2 = mb0 + 16;

    int v = blockIdx.y;
    int nb = blockIdx.x * BN;
    int t = threadIdx.x;
    int lane = t & 31;
    int ng = t >> 5;
    int n0 = ng * 8, c0 = lane * 4;

    if (t == 0) { MBAR_INIT(mb0); MBAR_INIT(mb1); MBAR_INIT(mb2); }
    __syncthreads();
    if (t == 0) {
        MBAR_EXPECT(mb0, 65536u);
        bulk_g2s(smaddr(W0), relW + (size_t)v * 16384, 65536u, mb0);
        MBAR_EXPECT(mb1, 65536u);
        bulk_g2s(smaddr(W1), gateW + (size_t)v * 16384, 65536u, mb1);
        MBAR_EXPECT(mb2, 32768u);
        bulk_g2s(smaddr(W2), vattW1, 32768u, mb2);
    }
    load_rows_warp(g_pre + (size_t)v * NN * 128, nb, n0, lane, Fs);
    float ws_r = 0.f;
    if (lane < 8) {
        int n = nb + n0 + lane;
        if (n < NN) ws_r = __ldg(g_wsum + v * NN + n);
    }
    __syncwarp();

    // ---- agg = pre @ relW + wsum * relb ----
    ull acc2[8][2];
    MBAR_WAIT(mb0, 0);
    ZERO_ACC(acc2);
    mm8x4<128>(Fs, W0 + c0, acc2, n0);
    {
        ulonglong2 r01 = __ldg(reinterpret_cast<const ulonglong2*>(relb + v * 128 + c0));
#pragma unroll
        for (int i = 0; i < 8; ++i) {
            ull wd = fdup(__shfl_sync(0xffffffffu, ws_r, i));
            ffma2(acc2[i][0], wd, r01.x);
            ffma2(acc2[i][1], wd, r01.y);
        }
    }
#pragma unroll
    for (int i = 0; i < 8; ++i) {
        float2 p0 = u2f(acc2[i][0]), p1 = u2f(acc2[i][1]);
        *reinterpret_cast<float4*>(Fs + (n0 + i) * 128 + c0) = make_float4(p0.x, p0.y, p1.x, p1.y);
    }
    __syncwarp();

    // ---- gate matmul on agg ----
    ull gac2[8][2];
    MBAR_WAIT(mb1, 0);
#pragma unroll
    for (int i = 0; i < 8; ++i) { gac2[i][0] = 0ull; gac2[i][1] = 0ull; }
    mm8x4<128>(Fs, W1 + c0, gac2, n0);

    {
        float4 gb = __ldg(reinterpret_cast<const float4*>(gateb + v * 128 + c0));
        float4 vp = __ldg(reinterpret_cast<const float4*>(view_pref + v * 128 + c0));
#pragma unroll
        for (int i = 0; i < 8; ++i) {
            int n = nb + n0 + i;
            float2 g0 = u2f(gac2[i][0]), g1 = u2f(gac2[i][1]);
            float2 a0 = u2f(acc2[i][0]), a1 = u2f(acc2[i][1]);
            float vo0 = sigm(g0.x + gb.x) * a0.x;
            float vo1 = sigm(g0.y + gb.y) * a0.y;
            float vo2 = sigm(g1.x + gb.z) * a1.x;
            float vo3 = sigm(g1.y + gb.w) * a1.y;
            if (n < NN)
                *reinterpret_cast<float4*>(g_viewout + ((size_t)v * NN + n) * 128 + c0) =
                    make_float4(vo0, vo1, vo2, vo3);
            *reinterpret_cast<float4*>(Fs + (n0 + i) * 128 + c0) =
                make_float4(vo0 * vp.x, vo1 * vp.y, vo2 * vp.z, vo3 * vp.w);
        }
    }
    __syncwarp();

    // ---- view-attention score ----
    ull vac[8];
    MBAR_WAIT(mb2, 0);
#pragma unroll
    for (int i = 0; i < 8; ++i) vac[i] = 0ull;
    mm8x2_64(Fs, W2 + lane * 2, vac, n0);
    {
        int cv = lane * 2;
        float2 vb = __ldg(reinterpret_cast<const float2*>(vattb1 + cv));
        float2 vw = __ldg(reinterpret_cast<const float2*>(vattW2 + cv));
        float b2v = __ldg(vattb2);
#pragma unroll
        for (int i = 0; i < 8; ++i) {
            float2 f0 = u2f(vac[i]);
            float s = fmaxf(f0.x + vb.x, 0.f) * vw.x + fmaxf(f0.y + vb.y, 0.f) * vw.y;
            s = wred32(s);
            int n = nb + n0 + i;
            if (lane == 0 && n < NN) g_vscore[v * NN + n] = s + b2v;
        }
    }
}

// ---------------- fusion + residual + layer norm (warp-synchronous after init) ----------------
__global__ void __launch_bounds__(NT, 1) k_fuse(
    const float* __restrict__ feats,
    const float* __restrict__ fusW,
    const float* __restrict__ ln_g, const float* __restrict__ ln_b,
    float* __restrict__ out) {
    extern __shared__ float sm[];
    float* Zs = sm + 8;
    float* W0 = Zs + 16384;
    float* W1 = W0 + 16384;
    unsigned mb0 = smaddr(sm), mb1 = mb0 + 8;

    int nb = blockIdx.x * BN;
    int t = threadIdx.x;
    int lane = t & 31;
    int ng = t >> 5;
    int n0 = ng * 8, c0 = lane * 4;

    if (t == 0) { MBAR_INIT(mb0); MBAR_INIT(mb1); }
    __syncthreads();
    if (t == 0) {
        MBAR_EXPECT(mb0, 65536u);
        bulk_g2s(smaddr(W0), g_W01, 65536u, mb0);
        MBAR_EXPECT(mb1, 65536u);
        bulk_g2s(smaddr(W1), fusW + 16384, 65536u, mb1);
    }
    float vw0_r = 0.f, vw1_r = 0.f, vw2_r = 0.f;
    if (lane < 8) {
        int n = nb + n0 + lane;
        float s0 = 0.f, s1 = 0.f, s2 = 0.f, na = 0.f;
        if (n < NN) {
            s0 = __ldg(g_vscore + n);
            s1 = __ldg(g_vscore + NN + n);
            s2 = __ldg(g_vscore + 2 * NN + n);
            na = __ldg(g_nodeatt + n);
        }
        float m = fmaxf(s0, fmaxf(s1, s2));
        float e0 = __expf(s0 - m), e1 = __expf(s1 - m), e2 = __expf(s2 - m);
        float inv = na / (e0 + e1 + e2);
        vw0_r = e0 * inv; vw1_r = e1 * inv; vw2_r = e2 * inv;
    }
    load_rows_warp(feats, nb, n0, lane, Zs);
    __syncwarp();

    // phase A: feats @ W01  (== self_out @ fusW[0:128))
    ull acc2[8][2];
    MBAR_WAIT(mb0, 0);
    ZERO_ACC(acc2);
    mm8x4<128>(Zs, W0 + c0, acc2, n0);

    // phase B: rebuild own rows = weighted view combo (warp-private)
#pragma unroll
    for (int i = 0; i < 8; ++i) {
        int nl = n0 + i;
        int n = nb + nl;
        float w0 = __shfl_sync(0xffffffffu, vw0_r, i);
        float w1 = __shfl_sync(0xffffffffu, vw1_r, i);
        float w2 = __shfl_sync(0xffffffffu, vw2_r, i);
        float4 a = make_float4(0.f, 0.f, 0.f, 0.f);
        if (n < NN) {
            float4 x0 = reinterpret_cast<const float4*>(g_viewout + (size_t)n * 128)[lane];
            float4 x1 = reinterpret_cast<const float4*>(g_viewout + ((size_t)NN + n) * 128)[lane];
            float4 x2 = reinterpret_cast<const float4*>(g_viewout + ((size_t)2 * NN + n) * 128)[lane];
            a.x = w0 * x0.x + w1 * x1.x + w2 * x2.x;
            a.y = w0 * x0.y + w1 * x1.y + w2 * x2.y;
            a.z = w0 * x0.z + w1 * x1.z + w2 * x2.z;
            a.w = w0 * x0.w + w1 * x1.w + w2 * x2.w;
        }
        reinterpret_cast<float4*>(Zs + nl * 128)[lane] = a;
    }
    __syncwarp();
    MBAR_WAIT(mb1, 0);
    mm8x4<128>(Zs, W1 + c0, acc2, n0);

    // epilogue: relu(+b01) + transformed, LN via warp reduce
    {
        float4 fb = __ldg(reinterpret_cast<const float4*>(g_b01 + c0));
        float4 lg = __ldg(reinterpret_cast<const float4*>(ln_g + c0));
        float4 lb = __ldg(reinterpret_cast<const float4*>(ln_b + c0));
#pragma unroll
        for (int i = 0; i < 8; ++i) {
            int n = nb + n0 + i;
            if (n >= NN) continue;   // uniform across warp
            float4 tr = *reinterpret_cast<const float4*>(g_transformed + (size_t)n * 128 + c0);
            float2 l0 = u2f(acc2[i][0]), l1 = u2f(acc2[i][1]);
            float f0 = fmaxf(l0.x + fb.x, 0.f) + tr.x;
            float f1 = fmaxf(l0.y + fb.y, 0.f) + tr.y;
            float f2 = fmaxf(l1.x + fb.z, 0.f) + tr.z;
            float f3 = fmaxf(l1.y + fb.w, 0.f) + tr.w;
            float s = f0 + f1 + f2 + f3;
            float s2 = f0 * f0 + f1 * f1 + f2 * f2 + f3 * f3;
            s = wred32(s);
            s2 = wred32(s2);
            float mu = s * (1.f / 128.f);
            float var = s2 * (1.f / 128.f) - mu * mu;
            float rs = rsqrtf(var + EPSL);
            *reinterpret_cast<float4*>(out + (size_t)n * 128 + c0) =
                make_float4((f0 - mu) * rs * lg.x + lb.x,
                            (f1 - mu) * rs * lg.y + lb.y,
                            (f2 - mu) * rs * lg.z + lb.z,
                            (f3 - mu) * rs * lg.w + lb.w);
        }
    }
}

// ---------------- launch ----------------
extern "C" void kernel_launch(void* const* d_in, const int* in_sizes, int n_in,
                              void* d_out, int out_size) {
    const float* feats   = (const float*)d_in[0];
    const int*   esrc    = (const int*)d_in[1];
    const int*   edst    = (const int*)d_in[2];
    const float* ew      = (const float*)d_in[3];
    const float* clsW    = (const float*)d_in[4];
    const float* clsb    = (const float*)d_in[5];
    const float* attW1   = (const float*)d_in[6];
    const float* attb1   = (const float*)d_in[7];
    const float* attW2   = (const float*)d_in[8];
    const float* attb2   = (const float*)d_in[9];
    const float* attbias = (const float*)d_in[10];
    const float* relW    = (const float*)d_in[11];
    const float* relb    = (const float*)d_in[12];
    const float* gateW   = (const float*)d_in[13];
    const float* gateb   = (const float*)d_in[14];
    const float* vpref   = (const float*)d_in[15];
    const float* vattW1  = (const float*)d_in[16];
    const float* vattb1  = (const float*)d_in[17];
    const float* vattW2  = (const float*)d_in[18];
    const float* vattb2  = (const float*)d_in[19];
    const float* selfW   = (const float*)d_in[20];
    const float* selfb   = (const float*)d_in[21];
    const float* featW   = (const float*)d_in[22];
    const float* featb   = (const float*)d_in[23];
    const float* fusW    = (const float*)d_in[24];
    const float* fusb    = (const float*)d_in[25];
    const float* lng     = (const float*)d_in[26];
    const float* lnb     = (const float*)d_in[27];

    float* out = (float*)d_out;
    float* out_cp = out + (size_t)NN * 128;

    const int SMEM_FEAT = (8 + 16384 * 3) * 4;
    const int SMEM_VIEW = (8 + 16384 * 3 + 8192) * 4;
    const int SMEM_FUSE = (8 + 16384 * 3) * 4;

    cudaFuncSetAttribute(k_feat, cudaFuncAttributeMaxDynamicSharedMemorySize, SMEM_FEAT);
    cudaFuncSetAttribute(k_view, cudaFuncAttributeMaxDynamicSharedMemorySize, SMEM_VIEW);
    cudaFuncSetAttribute(k_fuse, cudaFuncAttributeMaxDynamicSharedMemorySize, SMEM_FUSE);

    // ---- CSR build + gather (replaces zero + atomic edge scatter) ----
    k_zc<<<512, 256>>>();
    k_cnt<<<2048, 256>>>(edst);
    k_scan<<<1, 1024>>>();
    k_scatter<<<2048, 256>>>(esrc, edst, ew);
    {
        int blocks = (int)(((long long)VN * 32 + 255) / 256);
        k_gather<<<blocks, 256>>>(feats);
    }

    k_pre<<<128, 128>>>(selfW, selfb, fusW, fusb);

    k_feat<<<NTILES, NT, SMEM_FEAT>>>(feats, clsW, clsb, attW1, attb1, attW2, attb2,
                                      attbias, featW, featb, out_cp);

    dim3 gv(NTILES, VV);
    k_view<<<gv, NT, SMEM_VIEW>>>(relW, relb, gateW, gateb, vpref,
                                  vattW1, vattb1, vattW2, vattb2);

    k_fuse<<<NTILES, NT, SMEM_FUSE>>>(feats, fusW, lng, lnb, out);
}

// round 11
// speedup vs baseline: 1.1124x; 1.1124x over previous
#include <cuda_runtime.h>
#include <cstdint>

// ---------------- problem constants ----------------
#define NN 100000
#define VV 3
#define EE 500000
#define NE (VV * EE)
#define EPSL 1e-5f

#define BN 128         // nodes per tile (view/fuse kernels)
#define NT 512
#define NTILES ((NN + BN - 1) / BN)     // 782

#define BNF 96         // nodes per tile (fused feat+edge kernel, 12 GEMM warps)
#define NTILESF ((NN + BNF - 1) / BNF)  // 1042
#define EDGEW 4        // edge warps per block
#define TOTEW (NTILESF * EDGEW)

typedef unsigned long long ull;

// ---------------- scratch (device globals; no allocation) ----------------
__device__ float g_pre[(size_t)VV * NN * 128];
__device__ float g_wsum[VV * NN];
__device__ float g_transformed[(size_t)NN * 128];
__device__ float g_nodeatt[NN];
__device__ float g_viewout[(size_t)VV * NN * 128];
__device__ float g_vscore[VV * NN];
__device__ float g_W01[128 * 128];    // selfW @ fusW[0:128]
__device__ float g_b01[128];          // fusb + selfb @ fusW[0:128]

// ---------------- small helpers ----------------
__device__ __forceinline__ void ffma2(ull &d, ull a, ull b) {
    asm("fma.rn.f32x2 %0, %1, %2, %0;" : "+l"(d) : "l"(a), "l"(b));
}
__device__ __forceinline__ ull fdup(float a) {
    ull r; asm("mov.b64 %0, {%1, %1};" : "=l"(r) : "f"(a)); return r;
}
__device__ __forceinline__ float2 u2f(ull v) {
    float2 r; asm("mov.b64 {%0, %1}, %2;" : "=f"(r.x), "=f"(r.y) : "l"(v)); return r;
}
__device__ __forceinline__ float sigm(float x) { return 1.f / (1.f + __expf(-x)); }

__device__ __forceinline__ unsigned smaddr(const void* p) {
    unsigned r;
    asm("{ .reg .u64 t; cvta.to.shared.u64 t, %1; cvt.u32.u64 %0, t; }" : "=r"(r) : "l"(p));
    return r;
}
#define MBAR_INIT(a) asm volatile("mbarrier.init.shared.b64 [%0], 1;" :: "r"(a))
#define MBAR_EXPECT(a, bytes) \
    asm volatile("mbarrier.arrive.expect_tx.shared.b64 _, [%0], %1;" :: "r"(a), "r"(bytes))
#define MBAR_WAIT(a, parity) do { \
    unsigned _p = 0; \
    while (!_p) { \
        asm volatile("{\n\t.reg .pred P;\n\t" \
                     "mbarrier.try_wait.parity.shared.b64 P, [%1], %2, 0x989680;\n\t" \
                     "selp.u32 %0, 1, 0, P;\n\t}" \
                     : "=r"(_p) : "r"(a), "r"((unsigned)(parity))); \
    } } while (0)

__device__ __forceinline__ void bulk_g2s(unsigned dst, const void* src, unsigned bytes, unsigned mbar) {
    asm volatile("cp.async.bulk.shared::cluster.global.mbarrier::complete_tx::bytes [%0], [%1], %2, [%3];"
                 :: "r"(dst), "l"(src), "r"(bytes), "r"(mbar) : "memory");
}

__device__ __forceinline__ float wred32(float x) {
#pragma unroll
    for (int off = 16; off > 0; off >>= 1)
        x += __shfl_xor_sync(0xffffffffu, x, off);
    return x;
}
__device__ __forceinline__ float wred16(float x) {
#pragma unroll
    for (int off = 8; off > 0; off >>= 1)
        x += __shfl_xor_sync(0xffffffffu, x, off);
    return x;
}

// ---------------- zero scratch ----------------
__global__ void k_zero() {
    size_t tid = (size_t)blockIdx.x * blockDim.x + threadIdx.x;
    size_t stride = (size_t)gridDim.x * blockDim.x;
    size_t total4 = ((size_t)VV * NN * 128) / 4;
    float4 z = make_float4(0.f, 0.f, 0.f, 0.f);
    for (size_t i = tid; i < total4; i += stride)
        reinterpret_cast<float4*>(g_pre)[i] = z;
    for (size_t i = tid; i < (size_t)VV * NN; i += stride)
        g_wsum[i] = 0.f;
}

// ---------------- precompute W01 = selfW @ fusW[0:128), b01 = fusb + selfb @ fusW1 ----------------
__global__ void k_pre(const float* __restrict__ selfW, const float* __restrict__ selfb,
                      const float* __restrict__ fusW, const float* __restrict__ fusb) {
    int c = threadIdx.x;
    int i = blockIdx.x;
    float s = 0.f;
#pragma unroll 8
    for (int m = 0; m < 128; ++m)
        s = fmaf(selfW[i * 128 + m], __ldg(fusW + m * 128 + c), s);
    g_W01[i * 128 + c] = s;
    if (i == 0) {
        float b = __ldg(fusb + c);
#pragma unroll 8
        for (int m = 0; m < 128; ++m)
            b = fmaf(__ldg(selfb + m), __ldg(fusW + m * 128 + c), b);
        g_b01[c] = b;
    }
}

// ---------------- warp-private tile loader ----------------
__device__ __forceinline__ void load_rows_warp(const float* __restrict__ g, int nb, int n0,
                                               int lane, float* __restrict__ Fs) {
#pragma unroll
    for (int i = 0; i < 8; ++i) {
        int n = nb + n0 + i;
        float4 v = make_float4(0.f, 0.f, 0.f, 0.f);
        if (n < NN) v = reinterpret_cast<const float4*>(g + (size_t)n * 128)[lane];
        reinterpret_cast<float4*>(Fs + (n0 + i) * 128)[lane] = v;
    }
}

// ---------------- 8x4 register-blocked matmul, FFMA2, broadcast A ----------------
template <int BSTRIDE>
__device__ __forceinline__ void mm8x4(const float* __restrict__ Fs, const float* __restrict__ wbase,
                                      ull acc2[8][2], int n0) {
#pragma unroll 2
    for (int kk = 0; kk < 128; kk += 4) {
        float4 a4[8];
#pragma unroll
        for (int i = 0; i < 8; ++i)
            a4[i] = *reinterpret_cast<const float4*>(Fs + (n0 + i) * 128 + kk);
#pragma unroll
        for (int q = 0; q < 4; ++q) {
            ulonglong2 b = *reinterpret_cast<const ulonglong2*>(wbase + (kk + q) * BSTRIDE);
#pragma unroll
            for (int i = 0; i < 8; ++i) {
                float av = (q == 0) ? a4[i].x : (q == 1) ? a4[i].y : (q == 2) ? a4[i].z : a4[i].w;
                ull ad = fdup(av);
                ffma2(acc2[i][0], ad, b.x);
                ffma2(acc2[i][1], ad, b.y);
            }
        }
    }
}

__device__ __forceinline__ void mm8x2_64(const float* __restrict__ Fs, const float* __restrict__ wbase,
                                         ull acc[8], int n0) {
#pragma unroll 2
    for (int kk = 0; kk < 128; kk += 4) {
        float4 a4[8];
#pragma unroll
        for (int i = 0; i < 8; ++i)
            a4[i] = *reinterpret_cast<const float4*>(Fs + (n0 + i) * 128 + kk);
#pragma unroll
        for (int q = 0; q < 4; ++q) {
            ull b = *reinterpret_cast<const ull*>(wbase + (kk + q) * 64);
#pragma unroll
            for (int i = 0; i < 8; ++i) {
                float av = (q == 0) ? a4[i].x : (q == 1) ? a4[i].y : (q == 2) ? a4[i].z : a4[i].w;
                ffma2(acc[i], fdup(av), b);
            }
        }
    }
}

#define ZERO_ACC(acc2) do { \
    _Pragma("unroll") for (int i = 0; i < 8; ++i) { acc2[i][0] = 0ull; acc2[i][1] = 0ull; } } while (0)

// ---------------- fused feature + edge kernel ----------------
// 12 GEMM warps (BNF=96 node tile) + 4 edge-scatter warps per block.
// smem: [0:8) mbars | Fs 12288 | W0 16384 | W1 16384
__global__ void __launch_bounds__(NT, 1) k_featedge(
    const float* __restrict__ feats,
    const int* __restrict__ esrc, const int* __restrict__ edst, const float* __restrict__ ew,
    const float* __restrict__ clsW, const float* __restrict__ clsb,
    const float* __restrict__ attW1, const float* __restrict__ attb1,
    const float* __restrict__ attW2, const float* __restrict__ attb2,
    const float* __restrict__ attbias,
    const float* __restrict__ featW, const float* __restrict__ featb,
    float* __restrict__ out_cp) {
    extern __shared__ float sm[];
    float* Fs = sm + 8;
    float* W0 = Fs + BNF * 128;
    float* W1 = W0 + 16384;
    unsigned mb0 = smaddr(sm), mb1 = mb0 + 8;

    int nb = blockIdx.x * BNF;
    int t = threadIdx.x;
    int lane = t & 31;
    int ng = t >> 5;

    if (t == 0) { MBAR_INIT(mb0); MBAR_INIT(mb1); }
    __syncthreads();
    if (t == 0) {
        MBAR_EXPECT(mb0, 65536u);
        bulk_g2s(smaddr(W0), featW, 65536u, mb0);
        MBAR_EXPECT(mb1, 65536u);
        bulk_g2s(smaddr(W1), attW1, 65536u, mb1);
    }

    // ======== edge-scatter warps (ng 12..15) ========
    if (ng >= 12) {
        int ewid = blockIdx.x * EDGEW + (ng - 12);
        const int CH = (NE + TOTEW - 1) / TOTEW;
        int base = ewid * CH;
        int end = base + CH;
        if (end > NE) end = NE;
        for (int e = base; e < end; e += 4) {
            int m = end - e;
            if (m > 4) m = 4;
            int s[4], d[4], v[4];
            float wv[4];
#pragma unroll
            for (int j = 0; j < 4; ++j) {
                int idx = (j < m) ? e + j : e;
                s[j] = __ldg(esrc + idx);
                d[j] = __ldg(edst + idx);
                wv[j] = __ldg(ew + idx);
                v[j] = idx / EE;
            }
            float4 x[4];
#pragma unroll
            for (int j = 0; j < 4; ++j)
                x[j] = __ldg(reinterpret_cast<const float4*>(feats + (size_t)s[j] * 128) + lane);
#pragma unroll
            for (int j = 0; j < 4; ++j) {
                if (j < m) {
                    float* p = g_pre + ((size_t)v[j] * NN + d[j]) * 128 + lane * 4;
                    asm volatile("red.global.add.v4.f32 [%0], {%1,%2,%3,%4};" ::
                                 "l"(p), "f"(wv[j] * x[j].x), "f"(wv[j] * x[j].y),
                                 "f"(wv[j] * x[j].z), "f"(wv[j] * x[j].w) : "memory");
                    if (lane == 0) atomicAdd(&g_wsum[v[j] * NN + d[j]], wv[j]);
                }
            }
        }
        return;
    }

    // ======== GEMM warps (ng 0..11) ========
    int n0 = ng * 8, c0 = lane * 4;

    load_rows_warp(feats, nb, n0, lane, Fs);
    __syncwarp();

    ull acc2[8][2];

    // ---- transformed = f @ featW + featb ----
    MBAR_WAIT(mb0, 0);
    ZERO_ACC(acc2);
    mm8x4<128>(Fs, W0 + c0, acc2, n0);
    {
        float4 b0 = __ldg(reinterpret_cast<const float4*>(featb + c0));
#pragma unroll
        for (int i = 0; i < 8; ++i) {
            int n = nb + n0 + i;
            if (n < NN) {
                float2 p0 = u2f(acc2[i][0]), p1 = u2f(acc2[i][1]);
                *reinterpret_cast<float4*>(g_transformed + (size_t)n * 128 + c0) =
                    make_float4(p0.x + b0.x, p0.y + b0.y, p1.x + b0.z, p1.y + b0.w);
            }
        }
    }

    // ---- label attention ----
    float sc[8], sco[8];
    MBAR_WAIT(mb1, 0);
    ZERO_ACC(acc2);
    {
        int cls = c0 >> 6;
        mm8x4<64>(Fs, W1 + cls * 8192 + (c0 & 63), acc2, n0);
        float4 ab = __ldg(reinterpret_cast<const float4*>(attb1 + c0));
        float4 aw = __ldg(reinterpret_cast<const float4*>(attW2 + c0));
        float b2v = __ldg(attb2 + cls);
#pragma unroll
        for (int i = 0; i < 8; ++i) {
            float2 f0 = u2f(acc2[i][0]), f1 = u2f(acc2[i][1]);
            float p = fmaxf(f0.x + ab.x, 0.f) * aw.x
                    + fmaxf(f0.y + ab.y, 0.f) * aw.y
                    + fmaxf(f1.x + ab.z, 0.f) * aw.z
                    + fmaxf(f1.y + ab.w, 0.f) * aw.w;
            p = wred16(p);
            sc[i] = sigm(p + b2v);
            sco[i] = __shfl_xor_sync(0xffffffffu, sc[i], 16);
        }
    }

    // ---- class probs + node_att ----
    {
        float4 cw0 = __ldg(reinterpret_cast<const float4*>(clsW + c0 * 2));
        float4 cw1 = __ldg(reinterpret_cast<const float4*>(clsW + c0 * 2) + 1);
        float cb0 = __ldg(clsb), cb1 = __ldg(clsb + 1), abv = __ldg(attbias);
#pragma unroll
        for (int i = 0; i < 8; ++i) {
            float4 f = *reinterpret_cast<const float4*>(Fs + (n0 + i) * 128 + c0);
            float p0 = f.x * cw0.x + f.y * cw0.z + f.z * cw1.x + f.w * cw1.z;
            float p1 = f.x * cw0.y + f.y * cw0.w + f.z * cw1.y + f.w * cw1.w;
            p0 = wred32(p0);
            p1 = wred32(p1);
            int n = nb + n0 + i;
            if (lane == 0 && n < NN) {
                float l0 = p0 + cb0, l1 = p1 + cb1;
                float m = fmaxf(l0, l1);
                float e0 = __expf(l0 - m), e1 = __expf(l1 - m);
                float inv = 1.f / (e0 + e1);
                float cp0 = e0 * inv, cp1 = e1 * inv;
                out_cp[(size_t)n * 2] = cp0;
                out_cp[(size_t)n * 2 + 1] = cp1;
                g_nodeatt[n] = sc[i] * cp0 + sco[i] * cp1 + abv;
            }
        }
    }
}

// ---------------- per-view kernel (warp-synchronous after init) ----------------
// smem: [0:8) mbars | Fs 16384 | W0 16384 | W1 16384 | W2 8192
__global__ void __launch_bounds__(NT, 1) k_view(
    const float* __restrict__ relW, const float* __restrict__ relb,
    const float* __restrict__ gateW, const float* __restrict__ gateb,
    const float* __restrict__ view_pref,
    const float* __restrict__ vattW1, const float* __restrict__ vattb1,
    const float* __restrict__ vattW2, const float* __restrict__ vattb2) {
    extern __shared__ float sm[];
    float* Fs = sm + 8;
    float* W0 = Fs + 16384;
    float* W1 = W0 + 16384;
    float* W2 = W1 + 16384;
    unsigned mb0 = smaddr(sm), mb1 = mb0 + 8, mb2 = mb0 + 16;

    int v = blockIdx.y;
    int nb = blockIdx.x * BN;
    int t = threadIdx.x;
    int lane = t & 31;
    int ng = t >> 5;
    int n0 = ng * 8, c0 = lane * 4;

    if (t == 0) { MBAR_INIT(mb0); MBAR_INIT(mb1); MBAR_INIT(mb2); }
    __syncthreads();
    if (t == 0) {
        MBAR_EXPECT(mb0, 65536u);
        bulk_g2s(smaddr(W0), relW + (size_t)v * 16384, 65536u, mb0);
        MBAR_EXPECT(mb1, 65536u);
        bulk_g2s(smaddr(W1), gateW + (size_t)v * 16384, 65536u, mb1);
        MBAR_EXPECT(mb2, 32768u);
        bulk_g2s(smaddr(W2), vattW1, 32768u, mb2);
    }
    load_rows_warp(g_pre + (size_t)v * NN * 128, nb, n0, lane, Fs);
    float ws_r = 0.f;
    if (lane < 8) {
        int n = nb + n0 + lane;
        if (n < NN) ws_r = __ldg(g_wsum + v * NN + n);
    }
    __syncwarp();

    // ---- agg = pre @ relW + wsum * relb ----
    ull acc2[8][2];
    MBAR_WAIT(mb0, 0);
    ZERO_ACC(acc2);
    mm8x4<128>(Fs, W0 + c0, acc2, n0);
    {
        ulonglong2 r01 = __ldg(reinterpret_cast<const ulonglong2*>(relb + v * 128 + c0));
#pragma unroll
        for (int i = 0; i < 8; ++i) {
            ull wd = fdup(__shfl_sync(0xffffffffu, ws_r, i));
            ffma2(acc2[i][0], wd, r01.x);
            ffma2(acc2[i][1], wd, r01.y);
        }
    }
#pragma unroll
    for (int i = 0; i < 8; ++i) {
        float2 p0 = u2f(acc2[i][0]), p1 = u2f(acc2[i][1]);
        *reinterpret_cast<float4*>(Fs + (n0 + i) * 128 + c0) = make_float4(p0.x, p0.y, p1.x, p1.y);
    }
    __syncwarp();

    // ---- gate matmul on agg ----
    ull gac2[8][2];
    MBAR_WAIT(mb1, 0);
#pragma unroll
    for (int i = 0; i < 8; ++i) { gac2[i][0] = 0ull; gac2[i][1] = 0ull; }
    mm8x4<128>(Fs, W1 + c0, gac2, n0);

    {
        float4 gb = __ldg(reinterpret_cast<const float4*>(gateb + v * 128 + c0));
        float4 vp = __ldg(reinterpret_cast<const float4*>(view_pref + v * 128 + c0));
#pragma unroll
        for (int i = 0; i < 8; ++i) {
            int n = nb + n0 + i;
            float2 g0 = u2f(gac2[i][0]), g1 = u2f(gac2[i][1]);
            float2 a0 = u2f(acc2[i][0]), a1 = u2f(acc2[i][1]);
            float vo0 = sigm(g0.x + gb.x) * a0.x;
            float vo1 = sigm(g0.y + gb.y) * a0.y;
            float vo2 = sigm(g1.x + gb.z) * a1.x;
            float vo3 = sigm(g1.y + gb.w) * a1.y;
            if (n < NN)
                *reinterpret_cast<float4*>(g_viewout + ((size_t)v * NN + n) * 128 + c0) =
                    make_float4(vo0, vo1, vo2, vo3);
            *reinterpret_cast<float4*>(Fs + (n0 + i) * 128 + c0) =
                make_float4(vo0 * vp.x, vo1 * vp.y, vo2 * vp.z, vo3 * vp.w);
        }
    }
    __syncwarp();

    // ---- view-attention score ----
    ull vac[8];
    MBAR_WAIT(mb2, 0);
#pragma unroll
    for (int i = 0; i < 8; ++i) vac[i] = 0ull;
    mm8x2_64(Fs, W2 + lane * 2, vac, n0);
    {
        int cv = lane * 2;
        float2 vb = __ldg(reinterpret_cast<const float2*>(vattb1 + cv));
        float2 vw = __ldg(reinterpret_cast<const float2*>(vattW2 + cv));
        float b2v = __ldg(vattb2);
#pragma unroll
        for (int i = 0; i < 8; ++i) {
            float2 f0 = u2f(vac[i]);
            float s = fmaxf(f0.x + vb.x, 0.f) * vw.x + fmaxf(f0.y + vb.y, 0.f) * vw.y;
            s = wred32(s);
            int n = nb + n0 + i;
            if (lane == 0 && n < NN) g_vscore[v * NN + n] = s + b2v;
        }
    }
}

// ---------------- fusion + residual + layer norm (warp-synchronous after init) ----------------
__global__ void __launch_bounds__(NT, 1) k_fuse(
    const float* __restrict__ feats,
    const float* __restrict__ fusW,
    const float* __restrict__ ln_g, const float* __restrict__ ln_b,
    float* __restrict__ out) {
    extern __shared__ float sm[];
    float* Zs = sm + 8;
    float* W0 = Zs + 16384;
    float* W1 = W0 + 16384;
    unsigned mb0 = smaddr(sm), mb1 = mb0 + 8;

    int nb = blockIdx.x * BN;
    int t = threadIdx.x;
    int lane = t & 31;
    int ng = t >> 5;
    int n0 = ng * 8, c0 = lane * 4;

    if (t == 0) { MBAR_INIT(mb0); MBAR_INIT(mb1); }
    __syncthreads();
    if (t == 0) {
        MBAR_EXPECT(mb0, 65536u);
        bulk_g2s(smaddr(W0), g_W01, 65536u, mb0);
        MBAR_EXPECT(mb1, 65536u);
        bulk_g2s(smaddr(W1), fusW + 16384, 65536u, mb1);
    }
    float vw0_r = 0.f, vw1_r = 0.f, vw2_r = 0.f;
    if (lane < 8) {
        int n = nb + n0 + lane;
        float s0 = 0.f, s1 = 0.f, s2 = 0.f, na = 0.f;
        if (n < NN) {
            s0 = __ldg(g_vscore + n);
            s1 = __ldg(g_vscore + NN + n);
            s2 = __ldg(g_vscore + 2 * NN + n);
            na = __ldg(g_nodeatt + n);
        }
        float m = fmaxf(s0, fmaxf(s1, s2));
        float e0 = __expf(s0 - m), e1 = __expf(s1 - m), e2 = __expf(s2 - m);
        float inv = na / (e0 + e1 + e2);
        vw0_r = e0 * inv; vw1_r = e1 * inv; vw2_r = e2 * inv;
    }
    load_rows_warp(feats, nb, n0, lane, Zs);
    __syncwarp();

    // phase A: feats @ W01  (== self_out @ fusW[0:128))
    ull acc2[8][2];
    MBAR_WAIT(mb0, 0);
    ZERO_ACC(acc2);
    mm8x4<128>(Zs, W0 + c0, acc2, n0);

    // phase B: rebuild own rows = weighted view combo (warp-private)
#pragma unroll
    for (int i = 0; i < 8; ++i) {
        int nl = n0 + i;
        int n = nb + nl;
        float w0 = __shfl_sync(0xffffffffu, vw0_r, i);
        float w1 = __shfl_sync(0xffffffffu, vw1_r, i);
        float w2 = __shfl_sync(0xffffffffu, vw2_r, i);
        float4 a = make_float4(0.f, 0.f, 0.f, 0.f);
        if (n < NN) {
            float4 x0 = reinterpret_cast<const float4*>(g_viewout + (size_t)n * 128)[lane];
            float4 x1 = reinterpret_cast<const float4*>(g_viewout + ((size_t)NN + n) * 128)[lane];
            float4 x2 = reinterpret_cast<const float4*>(g_viewout + ((size_t)2 * NN + n) * 128)[lane];
            a.x = w0 * x0.x + w1 * x1.x + w2 * x2.x;
            a.y = w0 * x0.y + w1 * x1.y + w2 * x2.y;
            a.z = w0 * x0.z + w1 * x1.z + w2 * x2.z;
            a.w = w0 * x0.w + w1 * x1.w + w2 * x2.w;
        }
        reinterpret_cast<float4*>(Zs + nl * 128)[lane] = a;
    }
    __syncwarp();
    MBAR_WAIT(mb1, 0);
    mm8x4<128>(Zs, W1 + c0, acc2, n0);

    // epilogue: relu(+b01) + transformed, LN via warp reduce
    {
        float4 fb = __ldg(reinterpret_cast<const float4*>(g_b01 + c0));
        float4 lg = __ldg(reinterpret_cast<const float4*>(ln_g + c0));
        float4 lb = __ldg(reinterpret_cast<const float4*>(ln_b + c0));
#pragma unroll
        for (int i = 0; i < 8; ++i) {
            int n = nb + n0 + i;
            if (n >= NN) continue;   // uniform across warp
            float4 tr = *reinterpret_cast<const float4*>(g_transformed + (size_t)n * 128 + c0);
            float2 l0 = u2f(acc2[i][0]), l1 = u2f(acc2[i][1]);
            float f0 = fmaxf(l0.x + fb.x, 0.f) + tr.x;
            float f1 = fmaxf(l0.y + fb.y, 0.f) + tr.y;
            float f2 = fmaxf(l1.x + fb.z, 0.f) + tr.z;
            float f3 = fmaxf(l1.y + fb.w, 0.f) + tr.w;
            float s = f0 + f1 + f2 + f3;
            float s2 = f0 * f0 + f1 * f1 + f2 * f2 + f3 * f3;
            s = wred32(s);
            s2 = wred32(s2);
            float mu = s * (1.f / 128.f);
            float var = s2 * (1.f / 128.f) - mu * mu;
            float rs = rsqrtf(var + EPSL);
            *reinterpret_cast<float4*>(out + (size_t)n * 128 + c0) =
                make_float4((f0 - mu) * rs * lg.x + lb.x,
                            (f1 - mu) * rs * lg.y + lb.y,
                            (f2 - mu) * rs * lg.z + lb.z,
                            (f3 - mu) * rs * lg.w + lb.w);
        }
    }
}

// ---------------- launch ----------------
extern "C" void kernel_launch(void* const* d_in, const int* in_sizes, int n_in,
                              void* d_out, int out_size) {
    const float* feats   = (const float*)d_in[0];
    const int*   esrc    = (const int*)d_in[1];
    const int*   edst    = (const int*)d_in[2];
    const float* ew      = (const float*)d_in[3];
    const float* clsW    = (const float*)d_in[4];
    const float* clsb    = (const float*)d_in[5];
    const float* attW1   = (const float*)d_in[6];
    const float* attb1   = (const float*)d_in[7];
    const float* attW2   = (const float*)d_in[8];
    const float* attb2   = (const float*)d_in[9];
    const float* attbias = (const float*)d_in[10];
    const float* relW    = (const float*)d_in[11];
    const float* relb    = (const float*)d_in[12];
    const float* gateW   = (const float*)d_in[13];
    const float* gateb   = (const float*)d_in[14];
    const float* vpref   = (const float*)d_in[15];
    const float* vattW1  = (const float*)d_in[16];
    const float* vattb1  = (const float*)d_in[17];
    const float* vattW2  = (const float*)d_in[18];
    const float* vattb2  = (const float*)d_in[19];
    const float* selfW   = (const float*)d_in[20];
    const float* selfb   = (const float*)d_in[21];
    const float* featW   = (const float*)d_in[22];
    const float* featb   = (const float*)d_in[23];
    const float* fusW    = (const float*)d_in[24];
    const float* fusb    = (const float*)d_in[25];
    const float* lng     = (const float*)d_in[26];
    const float* lnb     = (const float*)d_in[27];

    float* out = (float*)d_out;
    float* out_cp = out + (size_t)NN * 128;

    const int SMEM_FE   = (8 + BNF * 128 + 16384 * 2) * 4;
    const int SMEM_VIEW = (8 + 16384 * 3 + 8192) * 4;
    const int SMEM_FUSE = (8 + 16384 * 3) * 4;

    cudaFuncSetAttribute(k_featedge, cudaFuncAttributeMaxDynamicSharedMemorySize, SMEM_FE);
    cudaFuncSetAttribute(k_view, cudaFuncAttributeMaxDynamicSharedMemorySize, SMEM_VIEW);
    cudaFuncSetAttribute(k_fuse, cudaFuncAttributeMaxDynamicSharedMemorySize, SMEM_FUSE);

    k_zero<<<2048, 256>>>();
    k_pre<<<128, 128>>>(selfW, selfb, fusW, fusb);

    // fused: feature-side GEMMs + edge scatter (independent, disjoint resources)
    k_featedge<<<NTILESF, NT, SMEM_FE>>>(feats, esrc, edst, ew,
                                         clsW, clsb, attW1, attb1, attW2, attb2,
                                         attbias, featW, featb, out_cp);

    dim3 gv(NTILES, VV);
    k_view<<<gv, NT, SMEM_VIEW>>>(relW, relb, gateW, gateb, vpref,
                                  vattW1, vattb1, vattW2, vattb2);

    k_fuse<<<NTILES, NT, SMEM_FUSE>>>(feats, fusW, lng, lnb, out);
}

// round 12
// speedup vs baseline: 1.3520x; 1.2154x over previous
#include <cuda_runtime.h>
#include <cstdint>

// ---------------- problem constants ----------------
#define NN 100000
#define VV 3
#define EE 500000
#define EPSL 1e-5f

#define BN 128         // nodes per tile
#define NT 512         // 16 warps; warp = 8-node row group
#define NTILES ((NN + BN - 1) / BN)   // 782

typedef unsigned long long ull;

// ---------------- scratch (device globals; no allocation) ----------------
__device__ float g_pre[(size_t)VV * NN * 128];
__device__ float g_wsum[VV * NN];
__device__ float g_transformed[(size_t)NN * 128];
__device__ float g_nodeatt[NN];
__device__ float g_viewout[(size_t)VV * NN * 128];
__device__ float g_vscore[VV * NN];
__device__ float g_W01[128 * 128];    // selfW @ fusW[0:128]
__device__ float g_b01[128];          // fusb + selfb @ fusW[0:128]
__device__ float g_RG[VV * 128 * 128];// relW[v] @ gateW[v]
__device__ float g_rbg[VV * 128];     // relb[v] @ gateW[v]

// ---------------- small helpers ----------------
__device__ __forceinline__ void ffma2(ull &d, ull a, ull b) {
    asm("fma.rn.f32x2 %0, %1, %2, %0;" : "+l"(d) : "l"(a), "l"(b));
}
__device__ __forceinline__ ull fdup(float a) {
    ull r; asm("mov.b64 %0, {%1, %1};" : "=l"(r) : "f"(a)); return r;
}
__device__ __forceinline__ float2 u2f(ull v) {
    float2 r; asm("mov.b64 {%0, %1}, %2;" : "=f"(r.x), "=f"(r.y) : "l"(v)); return r;
}
__device__ __forceinline__ float sigm(float x) { return 1.f / (1.f + __expf(-x)); }

__device__ __forceinline__ unsigned smaddr(const void* p) {
    unsigned r;
    asm("{ .reg .u64 t; cvta.to.shared.u64 t, %1; cvt.u32.u64 %0, t; }" : "=r"(r) : "l"(p));
    return r;
}
#define MBAR_INIT(a) asm volatile("mbarrier.init.shared.b64 [%0], 1;" :: "r"(a))
#define MBAR_EXPECT(a, bytes) \
    asm volatile("mbarrier.arrive.expect_tx.shared.b64 _, [%0], %1;" :: "r"(a), "r"(bytes))
#define MBAR_WAIT(a, parity) do { \
    unsigned _p = 0; \
    while (!_p) { \
        asm volatile("{\n\t.reg .pred P;\n\t" \
                     "mbarrier.try_wait.parity.shared.b64 P, [%1], %2, 0x989680;\n\t" \
                     "selp.u32 %0, 1, 0, P;\n\t}" \
                     : "=r"(_p) : "r"(a), "r"((unsigned)(parity))); \
    } } while (0)

__device__ __forceinline__ void bulk_g2s(unsigned dst, const void* src, unsigned bytes, unsigned mbar) {
    asm volatile("cp.async.bulk.shared::cluster.global.mbarrier::complete_tx::bytes [%0], [%1], %2, [%3];"
                 :: "r"(dst), "l"(src), "r"(bytes), "r"(mbar) : "memory");
}

__device__ __forceinline__ float wred32(float x) {
#pragma unroll
    for (int off = 16; off > 0; off >>= 1)
        x += __shfl_xor_sync(0xffffffffu, x, off);
    return x;
}
__device__ __forceinline__ float wred16(float x) {
#pragma unroll
    for (int off = 8; off > 0; off >>= 1)
        x += __shfl_xor_sync(0xffffffffu, x, off);
    return x;
}

// ---------------- zero scratch ----------------
__global__ void k_zero() {
    size_t tid = (size_t)blockIdx.x * blockDim.x + threadIdx.x;
    size_t stride = (size_t)gridDim.x * blockDim.x;
    size_t total4 = ((size_t)VV * NN * 128) / 4;
    float4 z = make_float4(0.f, 0.f, 0.f, 0.f);
    for (size_t i = tid; i < total4; i += stride)
        reinterpret_cast<float4*>(g_pre)[i] = z;
    for (size_t i = tid; i < (size_t)VV * NN; i += stride)
        g_wsum[i] = 0.f;
}

// ---------------- precompute W01 = selfW @ fusW[0:128), b01 = fusb + selfb @ fusW1 ----------------
__global__ void k_pre(const float* __restrict__ selfW, const float* __restrict__ selfb,
                      const float* __restrict__ fusW, const float* __restrict__ fusb) {
    int c = threadIdx.x;
    int i = blockIdx.x;
    float s = 0.f;
#pragma unroll 8
    for (int m = 0; m < 128; ++m)
        s = fmaf(selfW[i * 128 + m], __ldg(fusW + m * 128 + c), s);
    g_W01[i * 128 + c] = s;
    if (i == 0) {
        float b = __ldg(fusb + c);
#pragma unroll 8
        for (int m = 0; m < 128; ++m)
            b = fmaf(__ldg(selfb + m), __ldg(fusW + m * 128 + c), b);
        g_b01[c] = b;
    }
}

// ---------------- precompute RG[v] = relW[v] @ gateW[v], rbg[v] = relb[v] @ gateW[v] ----------------
__global__ void k_pre2(const float* __restrict__ relW, const float* __restrict__ relb,
                       const float* __restrict__ gateW) {
    int c = threadIdx.x;          // 0..127 output col
    int i = blockIdx.x;           // 0..127 input row
    int v = blockIdx.y;           // view
    const float* rw = relW + (size_t)v * 16384;
    const float* gw = gateW + (size_t)v * 16384;
    float s = 0.f;
#pragma unroll 8
    for (int m = 0; m < 128; ++m)
        s = fmaf(rw[i * 128 + m], __ldg(gw + m * 128 + c), s);
    g_RG[(size_t)v * 16384 + i * 128 + c] = s;
    if (i == 0) {
        float b = 0.f;
#pragma unroll 8
        for (int m = 0; m < 128; ++m)
            b = fmaf(__ldg(relb + v * 128 + m), __ldg(gw + m * 128 + c), b);
        g_rbg[v * 128 + c] = b;
    }
}

// ---------------- edge scatter ----------------
__global__ void __launch_bounds__(256) k_edge(const int* __restrict__ src,
                                              const int* __restrict__ dst,
                                              const float* __restrict__ w,
                                              const float* __restrict__ feats) {
    int gw = (int)(((size_t)blockIdx.x * 256 + threadIdx.x) >> 5);
    if (gw >= VV * EE) return;
    int l = threadIdx.x & 31;
    int v = gw / EE;
    int s = src[gw];
    int d = dst[gw];
    float we = w[gw];
    float4 x = reinterpret_cast<const float4*>(feats + (size_t)s * 128)[l];
    float* p = g_pre + ((size_t)v * NN + d) * 128 + l * 4;
    asm volatile("red.global.add.v4.f32 [%0], {%1,%2,%3,%4};" ::
                 "l"(p), "f"(we * x.x), "f"(we * x.y), "f"(we * x.z), "f"(we * x.w)
                 : "memory");
    if (l == 0) atomicAdd(&g_wsum[v * NN + d], we);
}

// ---------------- warp-private tile loader ----------------
__device__ __forceinline__ void load_rows_warp(const float* __restrict__ g, int nb, int n0,
                                               int lane, float* __restrict__ Fs) {
#pragma unroll
    for (int i = 0; i < 8; ++i) {
        int n = nb + n0 + i;
        float4 v = make_float4(0.f, 0.f, 0.f, 0.f);
        if (n < NN) v = reinterpret_cast<const float4*>(g + (size_t)n * 128)[lane];
        reinterpret_cast<float4*>(Fs + (n0 + i) * 128)[lane] = v;
    }
}

// ---------------- dual 8x4 matmul: two B matrices, shared A broadcast ----------------
template <int BS1, int BS2>
__device__ __forceinline__ void mm8x4_dual(const float* __restrict__ Fs,
                                           const float* __restrict__ w1,
                                           const float* __restrict__ w2,
                                           ull acc1[8][2], ull acc2[8][2], int n0) {
#pragma unroll 2
    for (int kk = 0; kk < 128; kk += 2) {
        float2 a2[8];
#pragma unroll
        for (int i = 0; i < 8; ++i)
            a2[i] = *reinterpret_cast<const float2*>(Fs + (n0 + i) * 128 + kk);
#pragma unroll
        for (int q = 0; q < 2; ++q) {
            ulonglong2 b1 = *reinterpret_cast<const ulonglong2*>(w1 + (kk + q) * BS1);
            ulonglong2 b2 = *reinterpret_cast<const ulonglong2*>(w2 + (kk + q) * BS2);
#pragma unroll
            for (int i = 0; i < 8; ++i) {
                ull ad = fdup(q ? a2[i].y : a2[i].x);
                ffma2(acc1[i][0], ad, b1.x);
                ffma2(acc1[i][1], ad, b1.y);
                ffma2(acc2[i][0], ad, b2.x);
                ffma2(acc2[i][1], ad, b2.y);
            }
        }
    }
}

// single 8x4 (for k_fuse)
template <int BSTRIDE>
__device__ __forceinline__ void mm8x4(const float* __restrict__ Fs, const float* __restrict__ wbase,
                                      ull acc2[8][2], int n0) {
#pragma unroll 2
    for (int kk = 0; kk < 128; kk += 4) {
        float4 a4[8];
#pragma unroll
        for (int i = 0; i < 8; ++i)
            a4[i] = *reinterpret_cast<const float4*>(Fs + (n0 + i) * 128 + kk);
#pragma unroll
        for (int q = 0; q < 4; ++q) {
            ulonglong2 b = *reinterpret_cast<const ulonglong2*>(wbase + (kk + q) * BSTRIDE);
#pragma unroll
            for (int i = 0; i < 8; ++i) {
                float av = (q == 0) ? a4[i].x : (q == 1) ? a4[i].y : (q == 2) ? a4[i].z : a4[i].w;
                ull ad = fdup(av);
                ffma2(acc2[i][0], ad, b.x);
                ffma2(acc2[i][1], ad, b.y);
            }
        }
    }
}

__device__ __forceinline__ void mm8x2_64(const float* __restrict__ Fs, const float* __restrict__ wbase,
                                         ull acc[8], int n0) {
#pragma unroll 2
    for (int kk = 0; kk < 128; kk += 4) {
        float4 a4[8];
#pragma unroll
        for (int i = 0; i < 8; ++i)
            a4[i] = *reinterpret_cast<const float4*>(Fs + (n0 + i) * 128 + kk);
#pragma unroll
        for (int q = 0; q < 4; ++q) {
            ull b = *reinterpret_cast<const ull*>(wbase + (kk + q) * 64);
#pragma unroll
            for (int i = 0; i < 8; ++i) {
                float av = (q == 0) ? a4[i].x : (q == 1) ? a4[i].y : (q == 2) ? a4[i].z : a4[i].w;
                ffma2(acc[i], fdup(av), b);
            }
        }
    }
}

#define ZERO_ACC(acc2) do { \
    _Pragma("unroll") for (int i = 0; i < 8; ++i) { acc2[i][0] = 0ull; acc2[i][1] = 0ull; } } while (0)

// ---------------- feature-side kernel: fused transformed + label-attention GEMMs ----------------
// smem: [0:8) mbars | Fs 16384 | W0 16384 | W1 16384
__global__ void __launch_bounds__(NT, 1) k_feat(
    const float* __restrict__ feats,
    const float* __restrict__ clsW, const float* __restrict__ clsb,
    const float* __restrict__ attW1, const float* __restrict__ attb1,
    const float* __restrict__ attW2, const float* __restrict__ attb2,
    const float* __restrict__ attbias,
    const float* __restrict__ featW, const float* __restrict__ featb,
    float* __restrict__ out_cp) {
    extern __shared__ float sm[];
    float* Fs = sm + 8;
    float* W0 = Fs + 16384;
    float* W1 = W0 + 16384;
    unsigned mb0 = smaddr(sm), mb1 = mb0 + 8;

    int nb = blockIdx.x * BN;
    int t = threadIdx.x;
    int lane = t & 31;
    int ng = t >> 5;
    int n0 = ng * 8, c0 = lane * 4;

    if (t == 0) { MBAR_INIT(mb0); MBAR_INIT(mb1); }
    __syncthreads();
    if (t == 0) {
        MBAR_EXPECT(mb0, 65536u);
        bulk_g2s(smaddr(W0), featW, 65536u, mb0);
        MBAR_EXPECT(mb1, 65536u);
        bulk_g2s(smaddr(W1), attW1, 65536u, mb1);
    }
    load_rows_warp(feats, nb, n0, lane, Fs);
    __syncwarp();

    ull acc_t[8][2], acc_l[8][2];
    ZERO_ACC(acc_t);
    ZERO_ACC(acc_l);

    MBAR_WAIT(mb0, 0);
    MBAR_WAIT(mb1, 0);
    {
        int cls = c0 >> 6;
        mm8x4_dual<128, 64>(Fs, W0 + c0, W1 + cls * 8192 + (c0 & 63), acc_t, acc_l, n0);
    }

    // ---- transformed = f @ featW + featb ----
    {
        float4 b0 = __ldg(reinterpret_cast<const float4*>(featb + c0));
#pragma unroll
        for (int i = 0; i < 8; ++i) {
            int n = nb + n0 + i;
            if (n < NN) {
                float2 p0 = u2f(acc_t[i][0]), p1 = u2f(acc_t[i][1]);
                *reinterpret_cast<float4*>(g_transformed + (size_t)n * 128 + c0) =
                    make_float4(p0.x + b0.x, p0.y + b0.y, p1.x + b0.z, p1.y + b0.w);
            }
        }
    }

    // ---- label attention scores ----
    float sc[8], sco[8];
    {
        int cls = c0 >> 6;
        float4 ab = __ldg(reinterpret_cast<const float4*>(attb1 + c0));
        float4 aw = __ldg(reinterpret_cast<const float4*>(attW2 + c0));
        float b2v = __ldg(attb2 + cls);
#pragma unroll
        for (int i = 0; i < 8; ++i) {
            float2 f0 = u2f(acc_l[i][0]), f1 = u2f(acc_l[i][1]);
            float p = fmaxf(f0.x + ab.x, 0.f) * aw.x
                    + fmaxf(f0.y + ab.y, 0.f) * aw.y
                    + fmaxf(f1.x + ab.z, 0.f) * aw.z
                    + fmaxf(f1.y + ab.w, 0.f) * aw.w;
            p = wred16(p);
            sc[i] = sigm(p + b2v);
            sco[i] = __shfl_xor_sync(0xffffffffu, sc[i], 16);
        }
    }

    // ---- class probs + node_att ----
    {
        float4 cw0 = __ldg(reinterpret_cast<const float4*>(clsW + c0 * 2));
        float4 cw1 = __ldg(reinterpret_cast<const float4*>(clsW + c0 * 2) + 1);
        float cb0 = __ldg(clsb), cb1 = __ldg(clsb + 1), abv = __ldg(attbias);
#pragma unroll
        for (int i = 0; i < 8; ++i) {
            float4 f = *reinterpret_cast<const float4*>(Fs + (n0 + i) * 128 + c0);
            float p0 = f.x * cw0.x + f.y * cw0.z + f.z * cw1.x + f.w * cw1.z;
            float p1 = f.x * cw0.y + f.y * cw0.w + f.z * cw1.y + f.w * cw1.w;
            p0 = wred32(p0);
            p1 = wred32(p1);
            int n = nb + n0 + i;
            if (lane == 0 && n < NN) {
                float l0 = p0 + cb0, l1 = p1 + cb1;
                float m = fmaxf(l0, l1);
                float e0 = __expf(l0 - m), e1 = __expf(l1 - m);
                float inv = 1.f / (e0 + e1);
                float cp0 = e0 * inv, cp1 = e1 * inv;
                out_cp[(size_t)n * 2] = cp0;
                out_cp[(size_t)n * 2 + 1] = cp1;
                g_nodeatt[n] = sc[i] * cp0 + sco[i] * cp1 + abv;
            }
        }
    }
}

// ---------------- per-view kernel: fused agg + gate GEMMs via RG ----------------
// smem: [0:8) mbars | Fs 16384 | W0 16384 | W1 16384 | W2 8192
__global__ void __launch_bounds__(NT, 1) k_view(
    const float* __restrict__ relW, const float* __restrict__ relb,
    const float* __restrict__ gateb,
    const float* __restrict__ view_pref,
    const float* __restrict__ vattW1, const float* __restrict__ vattb1,
    const float* __restrict__ vattW2, const float* __restrict__ vattb2) {
    extern __shared__ float sm[];
    float* Fs = sm + 8;
    float* W0 = Fs + 16384;
    float* W1 = W0 + 16384;
    float* W2 = W1 + 16384;
    unsigned mb0 = smaddr(sm), mb1 = mb0 + 8, mb2 = mb0 + 16;

    int v = blockIdx.y;
    int nb = blockIdx.x * BN;
    int t = threadIdx.x;
    int lane = t & 31;
    int ng = t >> 5;
    int n0 = ng * 8, c0 = lane * 4;

    if (t == 0) { MBAR_INIT(mb0); MBAR_INIT(mb1); MBAR_INIT(mb2); }
    __syncthreads();
    if (t == 0) {
        MBAR_EXPECT(mb0, 65536u);
        bulk_g2s(smaddr(W0), relW + (size_t)v * 16384, 65536u, mb0);
        MBAR_EXPECT(mb1, 65536u);
        bulk_g2s(smaddr(W1), g_RG + (size_t)v * 16384, 65536u, mb1);
        MBAR_EXPECT(mb2, 32768u);
        bulk_g2s(smaddr(W2), vattW1, 32768u, mb2);
    }
    load_rows_warp(g_pre + (size_t)v * NN * 128, nb, n0, lane, Fs);
    float ws_r = 0.f;
    if (lane < 8) {
        int n = nb + n0 + lane;
        if (n < NN) ws_r = __ldg(g_wsum + v * NN + n);
    }
    __syncwarp();

    // ---- fused: agg = pre@relW + wsum*relb ; gatelin = pre@RG + wsum*rbg ----
    ull acc_a[8][2], acc_g[8][2];
    ZERO_ACC(acc_a);
    ZERO_ACC(acc_g);
    MBAR_WAIT(mb0, 0);
    MBAR_WAIT(mb1, 0);
    mm8x4_dual<128, 128>(Fs, W0 + c0, W1 + c0, acc_a, acc_g, n0);
    {
        ulonglong2 r01 = __ldg(reinterpret_cast<const ulonglong2*>(relb + v * 128 + c0));
        ulonglong2 q01 = __ldg(reinterpret_cast<const ulonglong2*>(g_rbg + v * 128 + c0));
#pragma unroll
        for (int i = 0; i < 8; ++i) {
            ull wd = fdup(__shfl_sync(0xffffffffu, ws_r, i));
            ffma2(acc_a[i][0], wd, r01.x);
            ffma2(acc_a[i][1], wd, r01.y);
            ffma2(acc_g[i][0], wd, q01.x);
            ffma2(acc_g[i][1], wd, q01.y);
        }
    }

    // ---- view_out = sigm(gatelin + gateb) * agg; store + stash vo*vpref ----
    {
        float4 gb = __ldg(reinterpret_cast<const float4*>(gateb + v * 128 + c0));
        float4 vp = __ldg(reinterpret_cast<const float4*>(view_pref + v * 128 + c0));
#pragma unroll
        for (int i = 0; i < 8; ++i) {
            int n = nb + n0 + i;
            float2 g0 = u2f(acc_g[i][0]), g1 = u2f(acc_g[i][1]);
            float2 a0 = u2f(acc_a[i][0]), a1 = u2f(acc_a[i][1]);
            float vo0 = sigm(g0.x + gb.x) * a0.x;
            float vo1 = sigm(g0.y + gb.y) * a0.y;
            float vo2 = sigm(g1.x + gb.z) * a1.x;
            float vo3 = sigm(g1.y + gb.w) * a1.y;
            if (n < NN)
                *reinterpret_cast<float4*>(g_viewout + ((size_t)v * NN + n) * 128 + c0) =
                    make_float4(vo0, vo1, vo2, vo3);
            *reinterpret_cast<float4*>(Fs + (n0 + i) * 128 + c0) =
                make_float4(vo0 * vp.x, vo1 * vp.y, vo2 * vp.z, vo3 * vp.w);
        }
    }
    __syncwarp();

    // ---- view-attention score ----
    ull vac[8];
    MBAR_WAIT(mb2, 0);
#pragma unroll
    for (int i = 0; i < 8; ++i) vac[i] = 0ull;
    mm8x2_64(Fs, W2 + lane * 2, vac, n0);
    {
        int cv = lane * 2;
        float2 vb = __ldg(reinterpret_cast<const float2*>(vattb1 + cv));
        float2 vw = __ldg(reinterpret_cast<const float2*>(vattW2 + cv));
        float b2v = __ldg(vattb2);
#pragma unroll
        for (int i = 0; i < 8; ++i) {
            float2 f0 = u2f(vac[i]);
            float s = fmaxf(f0.x + vb.x, 0.f) * vw.x + fmaxf(f0.y + vb.y, 0.f) * vw.y;
            s = wred32(s);
            int n = nb + n0 + i;
            if (lane == 0 && n < NN) g_vscore[v * NN + n] = s + b2v;
        }
    }
}

// ---------------- fusion + residual + layer norm (warp-synchronous after init) ----------------
// smem: [0:8) mbars | Zs 16384 | W0 16384 | W1 16384
__global__ void __launch_bounds__(NT, 1) k_fuse(
    const float* __restrict__ feats,
    const float* __restrict__ fusW,
    const float* __restrict__ ln_g, const float* __restrict__ ln_b,
    float* __restrict__ out) {
    extern __shared__ float sm[];
    float* Zs = sm + 8;
    float* W0 = Zs + 16384;
    float* W1 = W0 + 16384;
    unsigned mb0 = smaddr(sm), mb1 = mb0 + 8;

    int nb = blockIdx.x * BN;
    int t = threadIdx.x;
    int lane = t & 31;
    int ng = t >> 5;
    int n0 = ng * 8, c0 = lane * 4;

    if (t == 0) { MBAR_INIT(mb0); MBAR_INIT(mb1); }
    __syncthreads();
    if (t == 0) {
        MBAR_EXPECT(mb0, 65536u);
        bulk_g2s(smaddr(W0), g_W01, 65536u, mb0);
        MBAR_EXPECT(mb1, 65536u);
        bulk_g2s(smaddr(W1), fusW + 16384, 65536u, mb1);
    }
    float vw0_r = 0.f, vw1_r = 0.f, vw2_r = 0.f;
    if (lane < 8) {
        int n = nb + n0 + lane;
        float s0 = 0.f, s1 = 0.f, s2 = 0.f, na = 0.f;
        if (n < NN) {
            s0 = __ldg(g_vscore + n);
            s1 = __ldg(g_vscore + NN + n);
            s2 = __ldg(g_vscore + 2 * NN + n);
            na = __ldg(g_nodeatt + n);
        }
        float m = fmaxf(s0, fmaxf(s1, s2));
        float e0 = __expf(s0 - m), e1 = __expf(s1 - m), e2 = __expf(s2 - m);
        float inv = na / (e0 + e1 + e2);
        vw0_r = e0 * inv; vw1_r = e1 * inv; vw2_r = e2 * inv;
    }
    load_rows_warp(feats, nb, n0, lane, Zs);
    __syncwarp();

    // phase A: feats @ W01  (== self_out @ fusW[0:128))
    ull acc2[8][2];
    MBAR_WAIT(mb0, 0);
    ZERO_ACC(acc2);
    mm8x4<128>(Zs, W0 + c0, acc2, n0);

    // phase B: rebuild own rows = weighted view combo (warp-private)
#pragma unroll
    for (int i = 0; i < 8; ++i) {
        int nl = n0 + i;
        int n = nb + nl;
        float w0 = __shfl_sync(0xffffffffu, vw0_r, i);
        float w1 = __shfl_sync(0xffffffffu, vw1_r, i);
        float w2 = __shfl_sync(0xffffffffu, vw2_r, i);
        float4 a = make_float4(0.f, 0.f, 0.f, 0.f);
        if (n < NN) {
            float4 x0 = reinterpret_cast<const float4*>(g_viewout + (size_t)n * 128)[lane];
            float4 x1 = reinterpret_cast<const float4*>(g_viewout + ((size_t)NN + n) * 128)[lane];
            float4 x2 = reinterpret_cast<const float4*>(g_viewout + ((size_t)2 * NN + n) * 128)[lane];
            a.x = w0 * x0.x + w1 * x1.x + w2 * x2.x;
            a.y = w0 * x0.y + w1 * x1.y + w2 * x2.y;
            a.z = w0 * x0.z + w1 * x1.z + w2 * x2.z;
            a.w = w0 * x0.w + w1 * x1.w + w2 * x2.w;
        }
        reinterpret_cast<float4*>(Zs + nl * 128)[lane] = a;
    }
    __syncwarp();
    MBAR_WAIT(mb1, 0);
    mm8x4<128>(Zs, W1 + c0, acc2, n0);

    // epilogue: relu(+b01) + transformed, LN via warp reduce
    {
        float4 fb = __ldg(reinterpret_cast<const float4*>(g_b01 + c0));
        float4 lg = __ldg(reinterpret_cast<const float4*>(ln_g + c0));
        float4 lb = __ldg(reinterpret_cast<const float4*>(ln_b + c0));
#pragma unroll
        for (int i = 0; i < 8; ++i) {
            int n = nb + n0 + i;
            if (n >= NN) continue;   // uniform across warp
            float4 tr = *reinterpret_cast<const float4*>(g_transformed + (size_t)n * 128 + c0);
            float2 l0 = u2f(acc2[i][0]), l1 = u2f(acc2[i][1]);
            float f0 = fmaxf(l0.x + fb.x, 0.f) + tr.x;
            float f1 = fmaxf(l0.y + fb.y, 0.f) + tr.y;
            float f2 = fmaxf(l1.x + fb.z, 0.f) + tr.z;
            float f3 = fmaxf(l1.y + fb.w, 0.f) + tr.w;
            float s = f0 + f1 + f2 + f3;
            float s2 = f0 * f0 + f1 * f1 + f2 * f2 + f3 * f3;
            s = wred32(s);
            s2 = wred32(s2);
            float mu = s * (1.f / 128.f);
            float var = s2 * (1.f / 128.f) - mu * mu;
            float rs = rsqrtf(var + EPSL);
            *reinterpret_cast<float4*>(out + (size_t)n * 128 + c0) =
                make_float4((f0 - mu) * rs * lg.x + lb.x,
                            (f1 - mu) * rs * lg.y + lb.y,
                            (f2 - mu) * rs * lg.z + lb.z,
                            (f3 - mu) * rs * lg.w + lb.w);
        }
    }
}

// ---------------- launch ----------------
extern "C" void kernel_launch(void* const* d_in, const int* in_sizes, int n_in,
                              void* d_out, int out_size) {
    const float* feats   = (const float*)d_in[0];
    const int*   esrc    = (const int*)d_in[1];
    const int*   edst    = (const int*)d_in[2];
    const float* ew      = (const float*)d_in[3];
    const float* clsW    = (const float*)d_in[4];
    const float* clsb    = (const float*)d_in[5];
    const float* attW1   = (const float*)d_in[6];
    const float* attb1   = (const float*)d_in[7];
    const float* attW2   = (const float*)d_in[8];
    const float* attb2   = (const float*)d_in[9];
    const float* attbias = (const float*)d_in[10];
    const float* relW    = (const float*)d_in[11];
    const float* relb    = (const float*)d_in[12];
    const float* gateW   = (const float*)d_in[13];
    const float* gateb   = (const float*)d_in[14];
    const float* vpref   = (const float*)d_in[15];
    const float* vattW1  = (const float*)d_in[16];
    const float* vattb1  = (const float*)d_in[17];
    const float* vattW2  = (const float*)d_in[18];
    const float* vattb2  = (const float*)d_in[19];
    const float* selfW   = (const float*)d_in[20];
    const float* selfb   = (const float*)d_in[21];
    const float* featW   = (const float*)d_in[22];
    const float* featb   = (const float*)d_in[23];
    const float* fusW    = (const float*)d_in[24];
    const float* fusb    = (const float*)d_in[25];
    const float* lng     = (const float*)d_in[26];
    const float* lnb     = (const float*)d_in[27];

    float* out = (float*)d_out;
    float* out_cp = out + (size_t)NN * 128;

    const int SMEM_FEAT = (8 + 16384 * 3) * 4;
    const int SMEM_VIEW = (8 + 16384 * 3 + 8192) * 4;
    const int SMEM_FUSE = (8 + 16384 * 3) * 4;

    cudaFuncSetAttribute(k_feat, cudaFuncAttributeMaxDynamicSharedMemorySize, SMEM_FEAT);
    cudaFuncSetAttribute(k_view, cudaFuncAttributeMaxDynamicSharedMemorySize, SMEM_VIEW);
    cudaFuncSetAttribute(k_fuse, cudaFuncAttributeMaxDynamicSharedMemorySize, SMEM_FUSE);

    k_zero<<<2048, 256>>>();
    k_pre<<<128, 128>>>(selfW, selfb, fusW, fusb);
    {
        dim3 g2(128, VV);
        k_pre2<<<g2, 128>>>(relW, relb, gateW);
    }

    {
        long long warps = (long long)VV * EE;
        int blocks = (int)((warps * 32 + 255) / 256);
        k_edge<<<blocks, 256>>>(esrc, edst, ew, feats);
    }

    k_feat<<<NTILES, NT, SMEM_FEAT>>>(feats, clsW, clsb, attW1, attb1, attW2, attb2,
                                      attbias, featW, featb, out_cp);

    dim3 gv(NTILES, VV);
    k_view<<<gv, NT, SMEM_VIEW>>>(relW, relb, gateb, vpref,
                                  vattW1, vattb1, vattW2, vattb2);

    k_fuse<<<NTILES, NT, SMEM_FUSE>>>(feats, fusW, lng, lnb, out);
}

// round 13
// speedup vs baseline: 1.3656x; 1.0101x over previous
#include <cuda_runtime.h>
#include <cstdint>

// ---------------- problem constants ----------------
#define NN 100000
#define VV 3
#define EE 500000
#define EPSL 1e-5f

#define BN 128         // nodes per tile
#define NT 512         // 16 warps; warp = 8-node row group
#define NTILES ((NN + BN - 1) / BN)   // 782

typedef unsigned long long ull;

// ---------------- scratch (device globals; no allocation) ----------------
__device__ float g_pre[(size_t)VV * NN * 128];
__device__ float g_wsum[VV * NN];
__device__ float g_transformed[(size_t)NN * 128];
__device__ float g_nodeatt[NN];
__device__ float g_viewout[(size_t)VV * NN * 128];
__device__ float g_vscore[VV * NN];
__device__ float g_W01[128 * 128];    // selfW @ fusW[0:128]
__device__ float g_b01[128];          // fusb + selfb @ fusW[0:128]
__device__ float g_RG[VV * 128 * 128];// relW[v] @ gateW[v]
__device__ float g_rbg[VV * 128];     // relb[v] @ gateW[v]

// ---------------- stream/event for parallel graph branches ----------------
struct BranchRes {
    cudaStream_t sB;
    cudaEvent_t eFork, eJoin;
    BranchRes() {
        cudaStreamCreateWithFlags(&sB, cudaStreamNonBlocking);
        cudaEventCreateWithFlags(&eFork, cudaEventDisableTiming);
        cudaEventCreateWithFlags(&eJoin, cudaEventDisableTiming);
    }
};
static BranchRes g_br;

// ---------------- small helpers ----------------
__device__ __forceinline__ void ffma2(ull &d, ull a, ull b) {
    asm("fma.rn.f32x2 %0, %1, %2, %0;" : "+l"(d) : "l"(a), "l"(b));
}
__device__ __forceinline__ ull fdup(float a) {
    ull r; asm("mov.b64 %0, {%1, %1};" : "=l"(r) : "f"(a)); return r;
}
__device__ __forceinline__ float2 u2f(ull v) {
    float2 r; asm("mov.b64 {%0, %1}, %2;" : "=f"(r.x), "=f"(r.y) : "l"(v)); return r;
}
__device__ __forceinline__ float sigm(float x) { return 1.f / (1.f + __expf(-x)); }

__device__ __forceinline__ unsigned smaddr(const void* p) {
    unsigned r;
    asm("{ .reg .u64 t; cvta.to.shared.u64 t, %1; cvt.u32.u64 %0, t; }" : "=r"(r) : "l"(p));
    return r;
}
#define MBAR_INIT(a) asm volatile("mbarrier.init.shared.b64 [%0], 1;" :: "r"(a))
#define MBAR_EXPECT(a, bytes) \
    asm volatile("mbarrier.arrive.expect_tx.shared.b64 _, [%0], %1;" :: "r"(a), "r"(bytes))
#define MBAR_WAIT(a, parity) do { \
    unsigned _p = 0; \
    while (!_p) { \
        asm volatile("{\n\t.reg .pred P;\n\t" \
                     "mbarrier.try_wait.parity.shared.b64 P, [%1], %2, 0x989680;\n\t" \
                     "selp.u32 %0, 1, 0, P;\n\t}" \
                     : "=r"(_p) : "r"(a), "r"((unsigned)(parity))); \
    } } while (0)

__device__ __forceinline__ void bulk_g2s(unsigned dst, const void* src, unsigned bytes, unsigned mbar) {
    asm volatile("cp.async.bulk.shared::cluster.global.mbarrier::complete_tx::bytes [%0], [%1], %2, [%3];"
                 :: "r"(dst), "l"(src), "r"(bytes), "r"(mbar) : "memory");
}

__device__ __forceinline__ float wred32(float x) {
#pragma unroll
    for (int off = 16; off > 0; off >>= 1)
        x += __shfl_xor_sync(0xffffffffu, x, off);
    return x;
}
__device__ __forceinline__ float wred16(float x) {
#pragma unroll
    for (int off = 8; off > 0; off >>= 1)
        x += __shfl_xor_sync(0xffffffffu, x, off);
    return x;
}

// ---------------- zero scratch ----------------
__global__ void k_zero() {
    size_t tid = (size_t)blockIdx.x * blockDim.x + threadIdx.x;
    size_t stride = (size_t)gridDim.x * blockDim.x;
    size_t total4 = ((size_t)VV * NN * 128) / 4;
    float4 z = make_float4(0.f, 0.f, 0.f, 0.f);
    for (size_t i = tid; i < total4; i += stride)
        reinterpret_cast<float4*>(g_pre)[i] = z;
    for (size_t i = tid; i < (size_t)VV * NN; i += stride)
        g_wsum[i] = 0.f;
}

// ---------------- precompute W01 = selfW @ fusW[0:128), b01 = fusb + selfb @ fusW1 ----------------
__global__ void k_pre(const float* __restrict__ selfW, const float* __restrict__ selfb,
                      const float* __restrict__ fusW, const float* __restrict__ fusb) {
    int c = threadIdx.x;
    int i = blockIdx.x;
    float s = 0.f;
#pragma unroll 8
    for (int m = 0; m < 128; ++m)
        s = fmaf(selfW[i * 128 + m], __ldg(fusW + m * 128 + c), s);
    g_W01[i * 128 + c] = s;
    if (i == 0) {
        float b = __ldg(fusb + c);
#pragma unroll 8
        for (int m = 0; m < 128; ++m)
            b = fmaf(__ldg(selfb + m), __ldg(fusW + m * 128 + c), b);
        g_b01[c] = b;
    }
}

// ---------------- precompute RG[v] = relW[v] @ gateW[v], rbg[v] = relb[v] @ gateW[v] ----------------
__global__ void k_pre2(const float* __restrict__ relW, const float* __restrict__ relb,
                       const float* __restrict__ gateW) {
    int c = threadIdx.x;
    int i = blockIdx.x;
    int v = blockIdx.y;
    const float* rw = relW + (size_t)v * 16384;
    const float* gw = gateW + (size_t)v * 16384;
    float s = 0.f;
#pragma unroll 8
    for (int m = 0; m < 128; ++m)
        s = fmaf(rw[i * 128 + m], __ldg(gw + m * 128 + c), s);
    g_RG[(size_t)v * 16384 + i * 128 + c] = s;
    if (i == 0) {
        float b = 0.f;
#pragma unroll 8
        for (int m = 0; m < 128; ++m)
            b = fmaf(__ldg(relb + v * 128 + m), __ldg(gw + m * 128 + c), b);
        g_rbg[v * 128 + c] = b;
    }
}

// ---------------- edge scatter ----------------
__global__ void __launch_bounds__(256) k_edge(const int* __restrict__ src,
                                              const int* __restrict__ dst,
                                              const float* __restrict__ w,
                                              const float* __restrict__ feats) {
    int gw = (int)(((size_t)blockIdx.x * 256 + threadIdx.x) >> 5);
    if (gw >= VV * EE) return;
    int l = threadIdx.x & 31;
    int v = gw / EE;
    int s = src[gw];
    int d = dst[gw];
    float we = w[gw];
    float4 x = reinterpret_cast<const float4*>(feats + (size_t)s * 128)[l];
    float* p = g_pre + ((size_t)v * NN + d) * 128 + l * 4;
    asm volatile("red.global.add.v4.f32 [%0], {%1,%2,%3,%4};" ::
                 "l"(p), "f"(we * x.x), "f"(we * x.y), "f"(we * x.z), "f"(we * x.w)
                 : "memory");
    if (l == 0) atomicAdd(&g_wsum[v * NN + d], we);
}

// ---------------- warp-private tile loader ----------------
__device__ __forceinline__ void load_rows_warp(const float* __restrict__ g, int nb, int n0,
                                               int lane, float* __restrict__ Fs) {
#pragma unroll
    for (int i = 0; i < 8; ++i) {
        int n = nb + n0 + i;
        float4 v = make_float4(0.f, 0.f, 0.f, 0.f);
        if (n < NN) v = reinterpret_cast<const float4*>(g + (size_t)n * 128)[lane];
        reinterpret_cast<float4*>(Fs + (n0 + i) * 128)[lane] = v;
    }
}

// ---------------- dual 8x4 matmul: two B matrices, shared A broadcast ----------------
template <int BS1, int BS2>
__device__ __forceinline__ void mm8x4_dual(const float* __restrict__ Fs,
                                           const float* __restrict__ w1,
                                           const float* __restrict__ w2,
                                           ull acc1[8][2], ull acc2[8][2], int n0) {
#pragma unroll 2
    for (int kk = 0; kk < 128; kk += 2) {
        float2 a2[8];
#pragma unroll
        for (int i = 0; i < 8; ++i)
            a2[i] = *reinterpret_cast<const float2*>(Fs + (n0 + i) * 128 + kk);
#pragma unroll
        for (int q = 0; q < 2; ++q) {
            ulonglong2 b1 = *reinterpret_cast<const ulonglong2*>(w1 + (kk + q) * BS1);
            ulonglong2 b2 = *reinterpret_cast<const ulonglong2*>(w2 + (kk + q) * BS2);
#pragma unroll
            for (int i = 0; i < 8; ++i) {
                ull ad = fdup(q ? a2[i].y : a2[i].x);
                ffma2(acc1[i][0], ad, b1.x);
                ffma2(acc1[i][1], ad, b1.y);
                ffma2(acc2[i][0], ad, b2.x);
                ffma2(acc2[i][1], ad, b2.y);
            }
        }
    }
}

// single 8x4 (for k_fuse)
template <int BSTRIDE>
__device__ __forceinline__ void mm8x4(const float* __restrict__ Fs, const float* __restrict__ wbase,
                                      ull acc2[8][2], int n0) {
#pragma unroll 2
    for (int kk = 0; kk < 128; kk += 4) {
        float4 a4[8];
#pragma unroll
        for (int i = 0; i < 8; ++i)
            a4[i] = *reinterpret_cast<const float4*>(Fs + (n0 + i) * 128 + kk);
#pragma unroll
        for (int q = 0; q < 4; ++q) {
            ulonglong2 b = *reinterpret_cast<const ulonglong2*>(wbase + (kk + q) * BSTRIDE);
#pragma unroll
            for (int i = 0; i < 8; ++i) {
                float av = (q == 0) ? a4[i].x : (q == 1) ? a4[i].y : (q == 2) ? a4[i].z : a4[i].w;
                ull ad = fdup(av);
                ffma2(acc2[i][0], ad, b.x);
                ffma2(acc2[i][1], ad, b.y);
            }
        }
    }
}

__device__ __forceinline__ void mm8x2_64(const float* __restrict__ Fs, const float* __restrict__ wbase,
                                         ull acc[8], int n0) {
#pragma unroll 2
    for (int kk = 0; kk < 128; kk += 4) {
        float4 a4[8];
#pragma unroll
        for (int i = 0; i < 8; ++i)
            a4[i] = *reinterpret_cast<const float4*>(Fs + (n0 + i) * 128 + kk);
#pragma unroll
        for (int q = 0; q < 4; ++q) {
            ull b = *reinterpret_cast<const ull*>(wbase + (kk + q) * 64);
#pragma unroll
            for (int i = 0; i < 8; ++i) {
                float av = (q == 0) ? a4[i].x : (q == 1) ? a4[i].y : (q == 2) ? a4[i].z : a4[i].w;
                ffma2(acc[i], fdup(av), b);
            }
        }
    }
}

#define ZERO_ACC(acc2) do { \
    _Pragma("unroll") for (int i = 0; i < 8; ++i) { acc2[i][0] = 0ull; acc2[i][1] = 0ull; } } while (0)

// ---------------- feature-side kernel: fused transformed + label-attention GEMMs ----------------
// smem: [0:8) mbars | Fs 16384 | W0 16384 | W1 16384
__global__ void __launch_bounds__(NT, 1) k_feat(
    const float* __restrict__ feats,
    const float* __restrict__ clsW, const float* __restrict__ clsb,
    const float* __restrict__ attW1, const float* __restrict__ attb1,
    const float* __restrict__ attW2, const float* __restrict__ attb2,
    const float* __restrict__ attbias,
    const float* __restrict__ featW, const float* __restrict__ featb,
    float* __restrict__ out_cp) {
    extern __shared__ float sm[];
    float* Fs = sm + 8;
    float* W0 = Fs + 16384;
    float* W1 = W0 + 16384;
    unsigned mb0 = smaddr(sm), mb1 = mb0 + 8;

    int nb = blockIdx.x * BN;
    int t = threadIdx.x;
    int lane = t & 31;
    int ng = t >> 5;
    int n0 = ng * 8, c0 = lane * 4;

    if (t == 0) { MBAR_INIT(mb0); MBAR_INIT(mb1); }
    __syncthreads();
    if (t == 0) {
        MBAR_EXPECT(mb0, 65536u);
        bulk_g2s(smaddr(W0), featW, 65536u, mb0);
        MBAR_EXPECT(mb1, 65536u);
        bulk_g2s(smaddr(W1), attW1, 65536u, mb1);
    }
    load_rows_warp(feats, nb, n0, lane, Fs);
    __syncwarp();

    ull acc_t[8][2], acc_l[8][2];
    ZERO_ACC(acc_t);
    ZERO_ACC(acc_l);

    MBAR_WAIT(mb0, 0);
    MBAR_WAIT(mb1, 0);
    {
        int cls = c0 >> 6;
        mm8x4_dual<128, 64>(Fs, W0 + c0, W1 + cls * 8192 + (c0 & 63), acc_t, acc_l, n0);
    }

    // ---- transformed = f @ featW + featb ----
    {
        float4 b0 = __ldg(reinterpret_cast<const float4*>(featb + c0));
#pragma unroll
        for (int i = 0; i < 8; ++i) {
            int n = nb + n0 + i;
            if (n < NN) {
                float2 p0 = u2f(acc_t[i][0]), p1 = u2f(acc_t[i][1]);
                *reinterpret_cast<float4*>(g_transformed + (size_t)n * 128 + c0) =
                    make_float4(p0.x + b0.x, p0.y + b0.y, p1.x + b0.z, p1.y + b0.w);
            }
        }
    }

    // ---- label attention scores ----
    float sc[8], sco[8];
    {
        int cls = c0 >> 6;
        float4 ab = __ldg(reinterpret_cast<const float4*>(attb1 + c0));
        float4 aw = __ldg(reinterpret_cast<const float4*>(attW2 + c0));
        float b2v = __ldg(attb2 + cls);
#pragma unroll
        for (int i = 0; i < 8; ++i) {
            float2 f0 = u2f(acc_l[i][0]), f1 = u2f(acc_l[i][1]);
            float p = fmaxf(f0.x + ab.x, 0.f) * aw.x
                    + fmaxf(f0.y + ab.y, 0.f) * aw.y
                    + fmaxf(f1.x + ab.z, 0.f) * aw.z
                    + fmaxf(f1.y + ab.w, 0.f) * aw.w;
            p = wred16(p);
            sc[i] = sigm(p + b2v);
            sco[i] = __shfl_xor_sync(0xffffffffu, sc[i], 16);
        }
    }

    // ---- class probs + node_att ----
    {
        float4 cw0 = __ldg(reinterpret_cast<const float4*>(clsW + c0 * 2));
        float4 cw1 = __ldg(reinterpret_cast<const float4*>(clsW + c0 * 2) + 1);
        float cb0 = __ldg(clsb), cb1 = __ldg(clsb + 1), abv = __ldg(attbias);
#pragma unroll
        for (int i = 0; i < 8; ++i) {
            float4 f = *reinterpret_cast<const float4*>(Fs + (n0 + i) * 128 + c0);
            float p0 = f.x * cw0.x + f.y * cw0.z + f.z * cw1.x + f.w * cw1.z;
            float p1 = f.x * cw0.y + f.y * cw0.w + f.z * cw1.y + f.w * cw1.w;
            p0 = wred32(p0);
            p1 = wred32(p1);
            int n = nb + n0 + i;
            if (lane == 0 && n < NN) {
                float l0 = p0 + cb0, l1 = p1 + cb1;
                float m = fmaxf(l0, l1);
                float e0 = __expf(l0 - m), e1 = __expf(l1 - m);
                float inv = 1.f / (e0 + e1);
                float cp0 = e0 * inv, cp1 = e1 * inv;
                out_cp[(size_t)n * 2] = cp0;
                out_cp[(size_t)n * 2 + 1] = cp1;
                g_nodeatt[n] = sc[i] * cp0 + sco[i] * cp1 + abv;
            }
        }
    }
}

// ---------------- per-view kernel: fused agg + gate GEMMs via RG ----------------
// smem: [0:8) mbars | Fs 16384 | W0 16384 | W1 16384 | W2 8192
__global__ void __launch_bounds__(NT, 1) k_view(
    const float* __restrict__ relW, const float* __restrict__ relb,
    const float* __restrict__ gateb,
    const float* __restrict__ view_pref,
    const float* __restrict__ vattW1, const float* __restrict__ vattb1,
    const float* __restrict__ vattW2, const float* __restrict__ vattb2) {
    extern __shared__ float sm[];
    float* Fs = sm + 8;
    float* W0 = Fs + 16384;
    float* W1 = W0 + 16384;
    float* W2 = W1 + 16384;
    unsigned mb0 = smaddr(sm), mb1 = mb0 + 8, mb2 = mb0 + 16;

    int v = blockIdx.y;
    int nb = blockIdx.x * BN;
    int t = threadIdx.x;
    int lane = t & 31;
    int ng = t >> 5;
    int n0 = ng * 8, c0 = lane * 4;

    if (t == 0) { MBAR_INIT(mb0); MBAR_INIT(mb1); MBAR_INIT(mb2); }
    __syncthreads();
    if (t == 0) {
        MBAR_EXPECT(mb0, 65536u);
        bulk_g2s(smaddr(W0), relW + (size_t)v * 16384, 65536u, mb0);
        MBAR_EXPECT(mb1, 65536u);
        bulk_g2s(smaddr(W1), g_RG + (size_t)v * 16384, 65536u, mb1);
        MBAR_EXPECT(mb2, 32768u);
        bulk_g2s(smaddr(W2), vattW1, 32768u, mb2);
    }
    load_rows_warp(g_pre + (size_t)v * NN * 128, nb, n0, lane, Fs);
    float ws_r = 0.f;
    if (lane < 8) {
        int n = nb + n0 + lane;
        if (n < NN) ws_r = __ldg(g_wsum + v * NN + n);
    }
    __syncwarp();

    // ---- fused: agg = pre@relW + wsum*relb ; gatelin = pre@RG + wsum*rbg ----
    ull acc_a[8][2], acc_g[8][2];
    ZERO_ACC(acc_a);
    ZERO_ACC(acc_g);
    MBAR_WAIT(mb0, 0);
    MBAR_WAIT(mb1, 0);
    mm8x4_dual<128, 128>(Fs, W0 + c0, W1 + c0, acc_a, acc_g, n0);
    {
        ulonglong2 r01 = __ldg(reinterpret_cast<const ulonglong2*>(relb + v * 128 + c0));
        ulonglong2 q01 = __ldg(reinterpret_cast<const ulonglong2*>(g_rbg + v * 128 + c0));
#pragma unroll
        for (int i = 0; i < 8; ++i) {
            ull wd = fdup(__shfl_sync(0xffffffffu, ws_r, i));
            ffma2(acc_a[i][0], wd, r01.x);
            ffma2(acc_a[i][1], wd, r01.y);
            ffma2(acc_g[i][0], wd, q01.x);
            ffma2(acc_g[i][1], wd, q01.y);
        }
    }

    // ---- view_out = sigm(gatelin + gateb) * agg; store + stash vo*vpref ----
    {
        float4 gb = __ldg(reinterpret_cast<const float4*>(gateb + v * 128 + c0));
        float4 vp = __ldg(reinterpret_cast<const float4*>(view_pref + v * 128 + c0));
#pragma unroll
        for (int i = 0; i < 8; ++i) {
            int n = nb + n0 + i;
            float2 g0 = u2f(acc_g[i][0]), g1 = u2f(acc_g[i][1]);
            float2 a0 = u2f(acc_a[i][0]), a1 = u2f(acc_a[i][1]);
            float vo0 = sigm(g0.x + gb.x) * a0.x;
            float vo1 = sigm(g0.y + gb.y) * a0.y;
            float vo2 = sigm(g1.x + gb.z) * a1.x;
            float vo3 = sigm(g1.y + gb.w) * a1.y;
            if (n < NN)
                *reinterpret_cast<float4*>(g_viewout + ((size_t)v * NN + n) * 128 + c0) =
                    make_float4(vo0, vo1, vo2, vo3);
            *reinterpret_cast<float4*>(Fs + (n0 + i) * 128 + c0) =
                make_float4(vo0 * vp.x, vo1 * vp.y, vo2 * vp.z, vo3 * vp.w);
        }
    }
    __syncwarp();

    // ---- view-attention score ----
    ull vac[8];
    MBAR_WAIT(mb2, 0);
#pragma unroll
    for (int i = 0; i < 8; ++i) vac[i] = 0ull;
    mm8x2_64(Fs, W2 + lane * 2, vac, n0);
    {
        int cv = lane * 2;
        float2 vb = __ldg(reinterpret_cast<const float2*>(vattb1 + cv));
        float2 vw = __ldg(reinterpret_cast<const float2*>(vattW2 + cv));
        float b2v = __ldg(vattb2);
#pragma unroll
        for (int i = 0; i < 8; ++i) {
            float2 f0 = u2f(vac[i]);
            float s = fmaxf(f0.x + vb.x, 0.f) * vw.x + fmaxf(f0.y + vb.y, 0.f) * vw.y;
            s = wred32(s);
            int n = nb + n0 + i;
            if (lane == 0 && n < NN) g_vscore[v * NN + n] = s + b2v;
        }
    }
}

// ---------------- fusion + residual + layer norm (warp-synchronous after init) ----------------
// smem: [0:8) mbars | Zs 16384 | W0 16384 | W1 16384
__global__ void __launch_bounds__(NT, 1) k_fuse(
    const float* __restrict__ feats,
    const float* __restrict__ fusW,
    const float* __restrict__ ln_g, const float* __restrict__ ln_b,
    float* __restrict__ out) {
    extern __shared__ float sm[];
    float* Zs = sm + 8;
    float* W0 = Zs + 16384;
    float* W1 = W0 + 16384;
    unsigned mb0 = smaddr(sm), mb1 = mb0 + 8;

    int nb = blockIdx.x * BN;
    int t = threadIdx.x;
    int lane = t & 31;
    int ng = t >> 5;
    int n0 = ng * 8, c0 = lane * 4;

    if (t == 0) { MBAR_INIT(mb0); MBAR_INIT(mb1); }
    __syncthreads();
    if (t == 0) {
        MBAR_EXPECT(mb0, 65536u);
        bulk_g2s(smaddr(W0), g_W01, 65536u, mb0);
        MBAR_EXPECT(mb1, 65536u);
        bulk_g2s(smaddr(W1), fusW + 16384, 65536u, mb1);
    }
    float vw0_r = 0.f, vw1_r = 0.f, vw2_r = 0.f;
    if (lane < 8) {
        int n = nb + n0 + lane;
        float s0 = 0.f, s1 = 0.f, s2 = 0.f, na = 0.f;
        if (n < NN) {
            s0 = __ldg(g_vscore + n);
            s1 = __ldg(g_vscore + NN + n);
            s2 = __ldg(g_vscore + 2 * NN + n);
            na = __ldg(g_nodeatt + n);
        }
        float m = fmaxf(s0, fmaxf(s1, s2));
        float e0 = __expf(s0 - m), e1 = __expf(s1 - m), e2 = __expf(s2 - m);
        float inv = na / (e0 + e1 + e2);
        vw0_r = e0 * inv; vw1_r = e1 * inv; vw2_r = e2 * inv;
    }
    load_rows_warp(feats, nb, n0, lane, Zs);
    __syncwarp();

    // phase A: feats @ W01  (== self_out @ fusW[0:128))
    ull acc2[8][2];
    MBAR_WAIT(mb0, 0);
    ZERO_ACC(acc2);
    mm8x4<128>(Zs, W0 + c0, acc2, n0);

    // phase B: rebuild own rows = weighted view combo (warp-private)
#pragma unroll
    for (int i = 0; i < 8; ++i) {
        int nl = n0 + i;
        int n = nb + nl;
        float w0 = __shfl_sync(0xffffffffu, vw0_r, i);
        float w1 = __shfl_sync(0xffffffffu, vw1_r, i);
        float w2 = __shfl_sync(0xffffffffu, vw2_r, i);
        float4 a = make_float4(0.f, 0.f, 0.f, 0.f);
        if (n < NN) {
            float4 x0 = reinterpret_cast<const float4*>(g_viewout + (size_t)n * 128)[lane];
            float4 x1 = reinterpret_cast<const float4*>(g_viewout + ((size_t)NN + n) * 128)[lane];
            float4 x2 = reinterpret_cast<const float4*>(g_viewout + ((size_t)2 * NN + n) * 128)[lane];
            a.x = w0 * x0.x + w1 * x1.x + w2 * x2.x;
            a.y = w0 * x0.y + w1 * x1.y + w2 * x2.y;
            a.z = w0 * x0.z + w1 * x1.z + w2 * x2.z;
            a.w = w0 * x0.w + w1 * x1.w + w2 * x2.w;
        }
        reinterpret_cast<float4*>(Zs + nl * 128)[lane] = a;
    }
    __syncwarp();
    MBAR_WAIT(mb1, 0);
    mm8x4<128>(Zs, W1 + c0, acc2, n0);

    // epilogue: relu(+b01) + transformed, LN via warp reduce
    {
        float4 fb = __ldg(reinterpret_cast<const float4*>(g_b01 + c0));
        float4 lg = __ldg(reinterpret_cast<const float4*>(ln_g + c0));
        float4 lb = __ldg(reinterpret_cast<const float4*>(ln_b + c0));
#pragma unroll
        for (int i = 0; i < 8; ++i) {
            int n = nb + n0 + i;
            if (n >= NN) continue;   // uniform across warp
            float4 tr = *reinterpret_cast<const float4*>(g_transformed + (size_t)n * 128 + c0);
            float2 l0 = u2f(acc2[i][0]), l1 = u2f(acc2[i][1]);
            float f0 = fmaxf(l0.x + fb.x, 0.f) + tr.x;
            float f1 = fmaxf(l0.y + fb.y, 0.f) + tr.y;
            float f2 = fmaxf(l1.x + fb.z, 0.f) + tr.z;
            float f3 = fmaxf(l1.y + fb.w, 0.f) + tr.w;
            float s = f0 + f1 + f2 + f3;
            float s2 = f0 * f0 + f1 * f1 + f2 * f2 + f3 * f3;
            s = wred32(s);
            s2 = wred32(s2);
            float mu = s * (1.f / 128.f);
            float var = s2 * (1.f / 128.f) - mu * mu;
            float rs = rsqrtf(var + EPSL);
            *reinterpret_cast<float4*>(out + (size_t)n * 128 + c0) =
                make_float4((f0 - mu) * rs * lg.x + lb.x,
                            (f1 - mu) * rs * lg.y + lb.y,
                            (f2 - mu) * rs * lg.z + lb.z,
                            (f3 - mu) * rs * lg.w + lb.w);
        }
    }
}

// ---------------- launch ----------------
extern "C" void kernel_launch(void* const* d_in, const int* in_sizes, int n_in,
                              void* d_out, int out_size) {
    const float* feats   = (const float*)d_in[0];
    const int*   esrc    = (const int*)d_in[1];
    const int*   edst    = (const int*)d_in[2];
    const float* ew      = (const float*)d_in[3];
    const float* clsW    = (const float*)d_in[4];
    const float* clsb    = (const float*)d_in[5];
    const float* attW1   = (const float*)d_in[6];
    const float* attb1   = (const float*)d_in[7];
    const float* attW2   = (const float*)d_in[8];
    const float* attb2   = (const float*)d_in[9];
    const float* attbias = (const float*)d_in[10];
    const float* relW    = (const float*)d_in[11];
    const float* relb    = (const float*)d_in[12];
    const float* gateW   = (const float*)d_in[13];
    const float* gateb   = (const float*)d_in[14];
    const float* vpref   = (const float*)d_in[15];
    const float* vattW1  = (const float*)d_in[16];
    const float* vattb1  = (const float*)d_in[17];
    const float* vattW2  = (const float*)d_in[18];
    const float* vattb2  = (const float*)d_in[19];
    const float* selfW   = (const float*)d_in[20];
    const float* selfb   = (const float*)d_in[21];
    const float* featW   = (const float*)d_in[22];
    const float* featb   = (const float*)d_in[23];
    const float* fusW    = (const float*)d_in[24];
    const float* fusb    = (const float*)d_in[25];
    const float* lng     = (const float*)d_in[26];
    const float* lnb     = (const float*)d_in[27];

    float* out = (float*)d_out;
    float* out_cp = out + (size_t)NN * 128;

    const int SMEM_FEAT = (8 + 16384 * 3) * 4;
    const int SMEM_VIEW = (8 + 16384 * 3 + 8192) * 4;
    const int SMEM_FUSE = (8 + 16384 * 3) * 4;

    cudaFuncSetAttribute(k_feat, cudaFuncAttributeMaxDynamicSharedMemorySize, SMEM_FEAT);
    cudaFuncSetAttribute(k_view, cudaFuncAttributeMaxDynamicSharedMemorySize, SMEM_VIEW);
    cudaFuncSetAttribute(k_fuse, cudaFuncAttributeMaxDynamicSharedMemorySize, SMEM_FUSE);

    // ---- fork: branch B (compute: pre, pre2, feat) runs parallel to branch A (zero, edge) ----
    cudaEventRecord(g_br.eFork, 0);
    cudaStreamWaitEvent(g_br.sB, g_br.eFork, 0);

    // branch B (stream sB)
    k_pre<<<128, 128, 0, g_br.sB>>>(selfW, selfb, fusW, fusb);
    {
        dim3 g2(128, VV);
        k_pre2<<<g2, 128, 0, g_br.sB>>>(relW, relb, gateW);
    }
    k_feat<<<NTILES, NT, SMEM_FEAT, g_br.sB>>>(feats, clsW, clsb, attW1, attb1, attW2, attb2,
                                               attbias, featW, featb, out_cp);
    cudaEventRecord(g_br.eJoin, g_br.sB);

    // branch A (legacy stream)
    k_zero<<<2048, 256>>>();
    {
        long long warps = (long long)VV * EE;
        int blocks = (int)((warps * 32 + 255) / 256);
        k_edge<<<blocks, 256>>>(esrc, edst, ew, feats);
    }

    // join: view needs g_pre (A) + g_RG (B); fuse needs view + feat + pre
    cudaStreamWaitEvent(0, g_br.eJoin, 0);

    dim3 gv(NTILES, VV);
    k_view<<<gv, NT, SMEM_VIEW>>>(relW, relb, gateb, vpref,
                                  vattW1, vattb1, vattW2, vattb2);

    k_fuse<<<NTILES, NT, SMEM_FUSE>>>(feats, fusW, lng, lnb, out);
}

// round 14
// speedup vs baseline: 1.4170x; 1.0376x over previous
#include <cuda_runtime.h>
#include <cstdint>

// ---------------- problem constants ----------------
#define NN 100000
#define VV 3
#define EE 500000
#define EPSL 1e-5f

#define BN 128         // nodes per tile
#define NT 512         // 16 warps; warp = 8-node row group
#define NTILES ((NN + BN - 1) / BN)   // 782

typedef unsigned long long ull;

// ---------------- scratch (device globals; no allocation) ----------------
__device__ float g_pre[(size_t)VV * NN * 128];
__device__ float g_wsum[VV * NN];
__device__ float g_transformed[(size_t)NN * 128];
__device__ float g_nodeatt[NN];
__device__ float g_viewout[(size_t)VV * NN * 128];
__device__ float g_vscore[VV * NN];
__device__ float g_W01[128 * 128];    // selfW @ fusW[0:128]
__device__ float g_b01[128];          // fusb + selfb @ fusW[0:128]
__device__ float g_RG[VV * 128 * 128];// relW[v] @ gateW[v]
__device__ float g_rbg[VV * 128];     // relb[v] @ gateW[v]

// ---------------- streams/events for pipelined graph ----------------
struct BranchRes {
    cudaStream_t sB, sV[VV];
    cudaEvent_t eFork, eRG, eFeat, eE[VV], eV[VV];
    BranchRes() {
        cudaStreamCreateWithFlags(&sB, cudaStreamNonBlocking);
        cudaEventCreateWithFlags(&eFork, cudaEventDisableTiming);
        cudaEventCreateWithFlags(&eRG, cudaEventDisableTiming);
        cudaEventCreateWithFlags(&eFeat, cudaEventDisableTiming);
        for (int v = 0; v < VV; ++v) {
            cudaStreamCreateWithFlags(&sV[v], cudaStreamNonBlocking);
            cudaEventCreateWithFlags(&eE[v], cudaEventDisableTiming);
            cudaEventCreateWithFlags(&eV[v], cudaEventDisableTiming);
        }
    }
};
static BranchRes g_br;

// ---------------- small helpers ----------------
__device__ __forceinline__ void ffma2(ull &d, ull a, ull b) {
    asm("fma.rn.f32x2 %0, %1, %2, %0;" : "+l"(d) : "l"(a), "l"(b));
}
__device__ __forceinline__ ull fdup(float a) {
    ull r; asm("mov.b64 %0, {%1, %1};" : "=l"(r) : "f"(a)); return r;
}
__device__ __forceinline__ float2 u2f(ull v) {
    float2 r; asm("mov.b64 {%0, %1}, %2;" : "=f"(r.x), "=f"(r.y) : "l"(v)); return r;
}
__device__ __forceinline__ float sigm(float x) { return 1.f / (1.f + __expf(-x)); }

__device__ __forceinline__ unsigned smaddr(const void* p) {
    unsigned r;
    asm("{ .reg .u64 t; cvta.to.shared.u64 t, %1; cvt.u32.u64 %0, t; }" : "=r"(r) : "l"(p));
    return r;
}
#define MBAR_INIT(a) asm volatile("mbarrier.init.shared.b64 [%0], 1;" :: "r"(a))
#define MBAR_EXPECT(a, bytes) \
    asm volatile("mbarrier.arrive.expect_tx.shared.b64 _, [%0], %1;" :: "r"(a), "r"(bytes))
#define MBAR_WAIT(a, parity) do { \
    unsigned _p = 0; \
    while (!_p) { \
        asm volatile("{\n\t.reg .pred P;\n\t" \
                     "mbarrier.try_wait.parity.shared.b64 P, [%1], %2, 0x989680;\n\t" \
                     "selp.u32 %0, 1, 0, P;\n\t}" \
                     : "=r"(_p) : "r"(a), "r"((unsigned)(parity))); \
    } } while (0)

__device__ __forceinline__ void bulk_g2s(unsigned dst, const void* src, unsigned bytes, unsigned mbar) {
    asm volatile("cp.async.bulk.shared::cluster.global.mbarrier::complete_tx::bytes [%0], [%1], %2, [%3];"
                 :: "r"(dst), "l"(src), "r"(bytes), "r"(mbar) : "memory");
}

__device__ __forceinline__ float wred32(float x) {
#pragma unroll
    for (int off = 16; off > 0; off >>= 1)
        x += __shfl_xor_sync(0xffffffffu, x, off);
    return x;
}
__device__ __forceinline__ float wred16(float x) {
#pragma unroll
    for (int off = 8; off > 0; off >>= 1)
        x += __shfl_xor_sync(0xffffffffu, x, off);
    return x;
}

// ---------------- zero one view's scratch ----------------
__global__ void k_zero_v(int v) {
    size_t tid = (size_t)blockIdx.x * blockDim.x + threadIdx.x;
    size_t stride = (size_t)gridDim.x * blockDim.x;
    float4 z = make_float4(0.f, 0.f, 0.f, 0.f);
    float4* base = reinterpret_cast<float4*>(g_pre + (size_t)v * NN * 128);
    for (size_t i = tid; i < (size_t)NN * 32; i += stride)
        base[i] = z;
    for (size_t i = tid; i < NN; i += stride)
        g_wsum[(size_t)v * NN + i] = 0.f;
}

// ---------------- precompute W01 = selfW @ fusW[0:128), b01 ----------------
__global__ void k_pre(const float* __restrict__ selfW, const float* __restrict__ selfb,
                      const float* __restrict__ fusW, const float* __restrict__ fusb) {
    int c = threadIdx.x;
    int i = blockIdx.x;
    float s = 0.f;
#pragma unroll 8
    for (int m = 0; m < 128; ++m)
        s = fmaf(selfW[i * 128 + m], __ldg(fusW + m * 128 + c), s);
    g_W01[i * 128 + c] = s;
    if (i == 0) {
        float b = __ldg(fusb + c);
#pragma unroll 8
        for (int m = 0; m < 128; ++m)
            b = fmaf(__ldg(selfb + m), __ldg(fusW + m * 128 + c), b);
        g_b01[c] = b;
    }
}

// ---------------- precompute RG[v], rbg[v] ----------------
__global__ void k_pre2(const float* __restrict__ relW, const float* __restrict__ relb,
                       const float* __restrict__ gateW) {
    int c = threadIdx.x;
    int i = blockIdx.x;
    int v = blockIdx.y;
    const float* rw = relW + (size_t)v * 16384;
    const float* gw = gateW + (size_t)v * 16384;
    float s = 0.f;
#pragma unroll 8
    for (int m = 0; m < 128; ++m)
        s = fmaf(rw[i * 128 + m], __ldg(gw + m * 128 + c), s);
    g_RG[(size_t)v * 16384 + i * 128 + c] = s;
    if (i == 0) {
        float b = 0.f;
#pragma unroll 8
        for (int m = 0; m < 128; ++m)
            b = fmaf(__ldg(relb + v * 128 + m), __ldg(gw + m * 128 + c), b);
        g_rbg[v * 128 + c] = b;
    }
}

// ---------------- edge scatter for one view ----------------
__global__ void __launch_bounds__(256) k_edge_v(int v,
                                                const int* __restrict__ src,
                                                const int* __restrict__ dst,
                                                const float* __restrict__ w,
                                                const float* __restrict__ feats) {
    int gw = (int)(((size_t)blockIdx.x * 256 + threadIdx.x) >> 5);
    if (gw >= EE) return;
    int l = threadIdx.x & 31;
    int s = src[gw];
    int d = dst[gw];
    float we = w[gw];
    float4 x = reinterpret_cast<const float4*>(feats + (size_t)s * 128)[l];
    float* p = g_pre + ((size_t)v * NN + d) * 128 + l * 4;
    asm volatile("red.global.add.v4.f32 [%0], {%1,%2,%3,%4};" ::
                 "l"(p), "f"(we * x.x), "f"(we * x.y), "f"(we * x.z), "f"(we * x.w)
                 : "memory");
    if (l == 0) atomicAdd(&g_wsum[v * NN + d], we);
}

// ---------------- warp-private tile loader ----------------
__device__ __forceinline__ void load_rows_warp(const float* __restrict__ g, int nb, int n0,
                                               int lane, float* __restrict__ Fs) {
#pragma unroll
    for (int i = 0; i < 8; ++i) {
        int n = nb + n0 + i;
        float4 v = make_float4(0.f, 0.f, 0.f, 0.f);
        if (n < NN) v = reinterpret_cast<const float4*>(g + (size_t)n * 128)[lane];
        reinterpret_cast<float4*>(Fs + (n0 + i) * 128)[lane] = v;
    }
}

// ---------------- dual 8x4 matmul: two B matrices, shared A broadcast ----------------
template <int BS1, int BS2>
__device__ __forceinline__ void mm8x4_dual(const float* __restrict__ Fs,
                                           const float* __restrict__ w1,
                                           const float* __restrict__ w2,
                                           ull acc1[8][2], ull acc2[8][2], int n0) {
#pragma unroll 2
    for (int kk = 0; kk < 128; kk += 2) {
        float2 a2[8];
#pragma unroll
        for (int i = 0; i < 8; ++i)
            a2[i] = *reinterpret_cast<const float2*>(Fs + (n0 + i) * 128 + kk);
#pragma unroll
        for (int q = 0; q < 2; ++q) {
            ulonglong2 b1 = *reinterpret_cast<const ulonglong2*>(w1 + (kk + q) * BS1);
            ulonglong2 b2 = *reinterpret_cast<const ulonglong2*>(w2 + (kk + q) * BS2);
#pragma unroll
            for (int i = 0; i < 8; ++i) {
                ull ad = fdup(q ? a2[i].y : a2[i].x);
                ffma2(acc1[i][0], ad, b1.x);
                ffma2(acc1[i][1], ad, b1.y);
                ffma2(acc2[i][0], ad, b2.x);
                ffma2(acc2[i][1], ad, b2.y);
            }
        }
    }
}

// single 8x4 (for k_fuse)
template <int BSTRIDE>
__device__ __forceinline__ void mm8x4(const float* __restrict__ Fs, const float* __restrict__ wbase,
                                      ull acc2[8][2], int n0) {
#pragma unroll 2
    for (int kk = 0; kk < 128; kk += 4) {
        float4 a4[8];
#pragma unroll
        for (int i = 0; i < 8; ++i)
            a4[i] = *reinterpret_cast<const float4*>(Fs + (n0 + i) * 128 + kk);
#pragma unroll
        for (int q = 0; q < 4; ++q) {
            ulonglong2 b = *reinterpret_cast<const ulonglong2*>(wbase + (kk + q) * BSTRIDE);
#pragma unroll
            for (int i = 0; i < 8; ++i) {
                float av = (q == 0) ? a4[i].x : (q == 1) ? a4[i].y : (q == 2) ? a4[i].z : a4[i].w;
                ull ad = fdup(av);
                ffma2(acc2[i][0], ad, b.x);
                ffma2(acc2[i][1], ad, b.y);
            }
        }
    }
}

__device__ __forceinline__ void mm8x2_64(const float* __restrict__ Fs, const float* __restrict__ wbase,
                                         ull acc[8], int n0) {
#pragma unroll 2
    for (int kk = 0; kk < 128; kk += 4) {
        float4 a4[8];
#pragma unroll
        for (int i = 0; i < 8; ++i)
            a4[i] = *reinterpret_cast<const float4*>(Fs + (n0 + i) * 128 + kk);
#pragma unroll
        for (int q = 0; q < 4; ++q) {
            ull b = *reinterpret_cast<const ull*>(wbase + (kk + q) * 64);
#pragma unroll
            for (int i = 0; i < 8; ++i) {
                float av = (q == 0) ? a4[i].x : (q == 1) ? a4[i].y : (q == 2) ? a4[i].z : a4[i].w;
                ffma2(acc[i], fdup(av), b);
            }
        }
    }
}

#define ZERO_ACC(acc2) do { \
    _Pragma("unroll") for (int i = 0; i < 8; ++i) { acc2[i][0] = 0ull; acc2[i][1] = 0ull; } } while (0)

// ---------------- feature-side kernel: fused transformed + label-attention GEMMs ----------------
// smem: [0:8) mbars | Fs 16384 | W0 16384 | W1 16384
__global__ void __launch_bounds__(NT, 1) k_feat(
    const float* __restrict__ feats,
    const float* __restrict__ clsW, const float* __restrict__ clsb,
    const float* __restrict__ attW1, const float* __restrict__ attb1,
    const float* __restrict__ attW2, const float* __restrict__ attb2,
    const float* __restrict__ attbias,
    const float* __restrict__ featW, const float* __restrict__ featb,
    float* __restrict__ out_cp) {
    extern __shared__ float sm[];
    float* Fs = sm + 8;
    float* W0 = Fs + 16384;
    float* W1 = W0 + 16384;
    unsigned mb0 = smaddr(sm), mb1 = mb0 + 8;

    int nb = blockIdx.x * BN;
    int t = threadIdx.x;
    int lane = t & 31;
    int ng = t >> 5;
    int n0 = ng * 8, c0 = lane * 4;

    if (t == 0) { MBAR_INIT(mb0); MBAR_INIT(mb1); }
    __syncthreads();
    if (t == 0) {
        MBAR_EXPECT(mb0, 65536u);
        bulk_g2s(smaddr(W0), featW, 65536u, mb0);
        MBAR_EXPECT(mb1, 65536u);
        bulk_g2s(smaddr(W1), attW1, 65536u, mb1);
    }
    load_rows_warp(feats, nb, n0, lane, Fs);
    __syncwarp();

    ull acc_t[8][2], acc_l[8][2];
    ZERO_ACC(acc_t);
    ZERO_ACC(acc_l);

    MBAR_WAIT(mb0, 0);
    MBAR_WAIT(mb1, 0);
    {
        int cls = c0 >> 6;
        mm8x4_dual<128, 64>(Fs, W0 + c0, W1 + cls * 8192 + (c0 & 63), acc_t, acc_l, n0);
    }

    // ---- transformed = f @ featW + featb ----
    {
        float4 b0 = __ldg(reinterpret_cast<const float4*>(featb + c0));
#pragma unroll
        for (int i = 0; i < 8; ++i) {
            int n = nb + n0 + i;
            if (n < NN) {
                float2 p0 = u2f(acc_t[i][0]), p1 = u2f(acc_t[i][1]);
                *reinterpret_cast<float4*>(g_transformed + (size_t)n * 128 + c0) =
                    make_float4(p0.x + b0.x, p0.y + b0.y, p1.x + b0.z, p1.y + b0.w);
            }
        }
    }

    // ---- label attention scores ----
    float sc[8], sco[8];
    {
        int cls = c0 >> 6;
        float4 ab = __ldg(reinterpret_cast<const float4*>(attb1 + c0));
        float4 aw = __ldg(reinterpret_cast<const float4*>(attW2 + c0));
        float b2v = __ldg(attb2 + cls);
#pragma unroll
        for (int i = 0; i < 8; ++i) {
            float2 f0 = u2f(acc_l[i][0]), f1 = u2f(acc_l[i][1]);
            float p = fmaxf(f0.x + ab.x, 0.f) * aw.x
                    + fmaxf(f0.y + ab.y, 0.f) * aw.y
                    + fmaxf(f1.x + ab.z, 0.f) * aw.z
                    + fmaxf(f1.y + ab.w, 0.f) * aw.w;
            p = wred16(p);
            sc[i] = sigm(p + b2v);
            sco[i] = __shfl_xor_sync(0xffffffffu, sc[i], 16);
        }
    }

    // ---- class probs + node_att ----
    {
        float4 cw0 = __ldg(reinterpret_cast<const float4*>(clsW + c0 * 2));
        float4 cw1 = __ldg(reinterpret_cast<const float4*>(clsW + c0 * 2) + 1);
        float cb0 = __ldg(clsb), cb1 = __ldg(clsb + 1), abv = __ldg(attbias);
#pragma unroll
        for (int i = 0; i < 8; ++i) {
            float4 f = *reinterpret_cast<const float4*>(Fs + (n0 + i) * 128 + c0);
            float p0 = f.x * cw0.x + f.y * cw0.z + f.z * cw1.x + f.w * cw1.z;
            float p1 = f.x * cw0.y + f.y * cw0.w + f.z * cw1.y + f.w * cw1.w;
            p0 = wred32(p0);
            p1 = wred32(p1);
            int n = nb + n0 + i;
            if (lane == 0 && n < NN) {
                float l0 = p0 + cb0, l1 = p1 + cb1;
                float m = fmaxf(l0, l1);
                float e0 = __expf(l0 - m), e1 = __expf(l1 - m);
                float inv = 1.f / (e0 + e1);
                float cp0 = e0 * inv, cp1 = e1 * inv;
                out_cp[(size_t)n * 2] = cp0;
                out_cp[(size_t)n * 2 + 1] = cp1;
                g_nodeatt[n] = sc[i] * cp0 + sco[i] * cp1 + abv;
            }
        }
    }
}

// ---------------- per-view kernel (v passed as arg; 1D grid) ----------------
// smem: [0:8) mbars | Fs 16384 | W0 16384 | W1 16384 | W2 8192
__global__ void __launch_bounds__(NT, 1) k_view(
    int v,
    const float* __restrict__ relW, const float* __restrict__ relb,
    const float* __restrict__ gateb,
    const float* __restrict__ view_pref,
    const float* __restrict__ vattW1, const float* __restrict__ vattb1,
    const float* __restrict__ vattW2, const float* __restrict__ vattb2) {
    extern __shared__ float sm[];
    float* Fs = sm + 8;
    float* W0 = Fs + 16384;
    float* W1 = W0 + 16384;
    float* W2 = W1 + 16384;
    unsigned mb0 = smaddr(sm), mb1 = mb0 + 8, mb2 = mb0 + 16;

    int nb = blockIdx.x * BN;
    int t = threadIdx.x;
    int lane = t & 31;
    int ng = t >> 5;
    int n0 = ng * 8, c0 = lane * 4;

    if (t == 0) { MBAR_INIT(mb0); MBAR_INIT(mb1); MBAR_INIT(mb2); }
    __syncthreads();
    if (t == 0) {
        MBAR_EXPECT(mb0, 65536u);
        bulk_g2s(smaddr(W0), relW + (size_t)v * 16384, 65536u, mb0);
        MBAR_EXPECT(mb1, 65536u);
        bulk_g2s(smaddr(W1), g_RG + (size_t)v * 16384, 65536u, mb1);
        MBAR_EXPECT(mb2, 32768u);
        bulk_g2s(smaddr(W2), vattW1, 32768u, mb2);
    }
    load_rows_warp(g_pre + (size_t)v * NN * 128, nb, n0, lane, Fs);
    float ws_r = 0.f;
    if (lane < 8) {
        int n = nb + n0 + lane;
        if (n < NN) ws_r = __ldg(g_wsum + v * NN + n);
    }
    __syncwarp();

    // ---- fused: agg = pre@relW + wsum*relb ; gatelin = pre@RG + wsum*rbg ----
    ull acc_a[8][2], acc_g[8][2];
    ZERO_ACC(acc_a);
    ZERO_ACC(acc_g);
    MBAR_WAIT(mb0, 0);
    MBAR_WAIT(mb1, 0);
    mm8x4_dual<128, 128>(Fs, W0 + c0, W1 + c0, acc_a, acc_g, n0);
    {
        ulonglong2 r01 = __ldg(reinterpret_cast<const ulonglong2*>(relb + v * 128 + c0));
        ulonglong2 q01 = __ldg(reinterpret_cast<const ulonglong2*>(g_rbg + v * 128 + c0));
#pragma unroll
        for (int i = 0; i < 8; ++i) {
            ull wd = fdup(__shfl_sync(0xffffffffu, ws_r, i));
            ffma2(acc_a[i][0], wd, r01.x);
            ffma2(acc_a[i][1], wd, r01.y);
            ffma2(acc_g[i][0], wd, q01.x);
            ffma2(acc_g[i][1], wd, q01.y);
        }
    }

    // ---- view_out = sigm(gatelin + gateb) * agg; store + stash vo*vpref ----
    {
        float4 gb = __ldg(reinterpret_cast<const float4*>(gateb + v * 128 + c0));
        float4 vp = __ldg(reinterpret_cast<const float4*>(view_pref + v * 128 + c0));
#pragma unroll
        for (int i = 0; i < 8; ++i) {
            int n = nb + n0 + i;
            float2 g0 = u2f(acc_g[i][0]), g1 = u2f(acc_g[i][1]);
            float2 a0 = u2f(acc_a[i][0]), a1 = u2f(acc_a[i][1]);
            float vo0 = sigm(g0.x + gb.x) * a0.x;
            float vo1 = sigm(g0.y + gb.y) * a0.y;
            float vo2 = sigm(g1.x + gb.z) * a1.x;
            float vo3 = sigm(g1.y + gb.w) * a1.y;
            if (n < NN)
                *reinterpret_cast<float4*>(g_viewout + ((size_t)v * NN + n) * 128 + c0) =
                    make_float4(vo0, vo1, vo2, vo3);
            *reinterpret_cast<float4*>(Fs + (n0 + i) * 128 + c0) =
                make_float4(vo0 * vp.x, vo1 * vp.y, vo2 * vp.z, vo3 * vp.w);
        }
    }
    __syncwarp();

    // ---- view-attention score ----
    ull vac[8];
    MBAR_WAIT(mb2, 0);
#pragma unroll
    for (int i = 0; i < 8; ++i) vac[i] = 0ull;
    mm8x2_64(Fs, W2 + lane * 2, vac, n0);
    {
        int cv = lane * 2;
        float2 vb = __ldg(reinterpret_cast<const float2*>(vattb1 + cv));
        float2 vw = __ldg(reinterpret_cast<const float2*>(vattW2 + cv));
        float b2v = __ldg(vattb2);
#pragma unroll
        for (int i = 0; i < 8; ++i) {
            float2 f0 = u2f(vac[i]);
            float s = fmaxf(f0.x + vb.x, 0.f) * vw.x + fmaxf(f0.y + vb.y, 0.f) * vw.y;
            s = wred32(s);
            int n = nb + n0 + i;
            if (lane == 0 && n < NN) g_vscore[v * NN + n] = s + b2v;
        }
    }
}

// ---------------- fusion + residual + layer norm ----------------
// smem: [0:8) mbars | Zs 16384 | W0 16384 | W1 16384
__global__ void __launch_bounds__(NT, 1) k_fuse(
    const float* __restrict__ feats,
    const float* __restrict__ fusW,
    const float* __restrict__ ln_g, const float* __restrict__ ln_b,
    float* __restrict__ out) {
    extern __shared__ float sm[];
    float* Zs = sm + 8;
    float* W0 = Zs + 16384;
    float* W1 = W0 + 16384;
    unsigned mb0 = smaddr(sm), mb1 = mb0 + 8;

    int nb = blockIdx.x * BN;
    int t = threadIdx.x;
    int lane = t & 31;
    int ng = t >> 5;
    int n0 = ng * 8, c0 = lane * 4;

    if (t == 0) { MBAR_INIT(mb0); MBAR_INIT(mb1); }
    __syncthreads();
    if (t == 0) {
        MBAR_EXPECT(mb0, 65536u);
        bulk_g2s(smaddr(W0), g_W01, 65536u, mb0);
        MBAR_EXPECT(mb1, 65536u);
        bulk_g2s(smaddr(W1), fusW + 16384, 65536u, mb1);
    }
    float vw0_r = 0.f, vw1_r = 0.f, vw2_r = 0.f;
    if (lane < 8) {
        int n = nb + n0 + lane;
        float s0 = 0.f, s1 = 0.f, s2 = 0.f, na = 0.f;
        if (n < NN) {
            s0 = __ldg(g_vscore + n);
            s1 = __ldg(g_vscore + NN + n);
            s2 = __ldg(g_vscore + 2 * NN + n);
            na = __ldg(g_nodeatt + n);
        }
        float m = fmaxf(s0, fmaxf(s1, s2));
        float e0 = __expf(s0 - m), e1 = __expf(s1 - m), e2 = __expf(s2 - m);
        float inv = na / (e0 + e1 + e2);
        vw0_r = e0 * inv; vw1_r = e1 * inv; vw2_r = e2 * inv;
    }
    load_rows_warp(feats, nb, n0, lane, Zs);
    __syncwarp();

    // phase A: feats @ W01  (== self_out @ fusW[0:128))
    ull acc2[8][2];
    MBAR_WAIT(mb0, 0);
    ZERO_ACC(acc2);
    mm8x4<128>(Zs, W0 + c0, acc2, n0);

    // phase B: rebuild own rows = weighted view combo (warp-private)
#pragma unroll
    for (int i = 0; i < 8; ++i) {
        int nl = n0 + i;
        int n = nb + nl;
        float w0 = __shfl_sync(0xffffffffu, vw0_r, i);
        float w1 = __shfl_sync(0xffffffffu, vw1_r, i);
        float w2 = __shfl_sync(0xffffffffu, vw2_r, i);
        float4 a = make_float4(0.f, 0.f, 0.f, 0.f);
        if (n < NN) {
            float4 x0 = reinterpret_cast<const float4*>(g_viewout + (size_t)n * 128)[lane];
            float4 x1 = reinterpret_cast<const float4*>(g_viewout + ((size_t)NN + n) * 128)[lane];
            float4 x2 = reinterpret_cast<const float4*>(g_viewout + ((size_t)2 * NN + n) * 128)[lane];
            a.x = w0 * x0.x + w1 * x1.x + w2 * x2.x;
            a.y = w0 * x0.y + w1 * x1.y + w2 * x2.y;
            a.z = w0 * x0.z + w1 * x1.z + w2 * x2.z;
            a.w = w0 * x0.w + w1 * x1.w + w2 * x2.w;
        }
        reinterpret_cast<float4*>(Zs + nl * 128)[lane] = a;
    }
    __syncwarp();
    MBAR_WAIT(mb1, 0);
    mm8x4<128>(Zs, W1 + c0, acc2, n0);

    // epilogue: relu(+b01) + transformed, LN via warp reduce
    {
        float4 fb = __ldg(reinterpret_cast<const float4*>(g_b01 + c0));
        float4 lg = __ldg(reinterpret_cast<const float4*>(ln_g + c0));
        float4 lb = __ldg(reinterpret_cast<const float4*>(ln_b + c0));
#pragma unroll
        for (int i = 0; i < 8; ++i) {
            int n = nb + n0 + i;
            if (n >= NN) continue;   // uniform across warp
            float4 tr = *reinterpret_cast<const float4*>(g_transformed + (size_t)n * 128 + c0);
            float2 l0 = u2f(acc2[i][0]), l1 = u2f(acc2[i][1]);
            float f0 = fmaxf(l0.x + fb.x, 0.f) + tr.x;
            float f1 = fmaxf(l0.y + fb.y, 0.f) + tr.y;
            float f2 = fmaxf(l1.x + fb.z, 0.f) + tr.z;
            float f3 = fmaxf(l1.y + fb.w, 0.f) + tr.w;
            float s = f0 + f1 + f2 + f3;
            float s2 = f0 * f0 + f1 * f1 + f2 * f2 + f3 * f3;
            s = wred32(s);
            s2 = wred32(s2);
            float mu = s * (1.f / 128.f);
            float var = s2 * (1.f / 128.f) - mu * mu;
            float rs = rsqrtf(var + EPSL);
            *reinterpret_cast<float4*>(out + (size_t)n * 128 + c0) =
                make_float4((f0 - mu) * rs * lg.x + lb.x,
                            (f1 - mu) * rs * lg.y + lb.y,
                            (f2 - mu) * rs * lg.z + lb.z,
                            (f3 - mu) * rs * lg.w + lb.w);
        }
    }
}

// ---------------- launch ----------------
extern "C" void kernel_launch(void* const* d_in, const int* in_sizes, int n_in,
                              void* d_out, int out_size) {
    const float* feats   = (const float*)d_in[0];
    const int*   esrc    = (const int*)d_in[1];
    const int*   edst    = (const int*)d_in[2];
    const float* ew      = (const float*)d_in[3];
    const float* clsW    = (const float*)d_in[4];
    const float* clsb    = (const float*)d_in[5];
    const float* attW1   = (const float*)d_in[6];
    const float* attb1   = (const float*)d_in[7];
    const float* attW2   = (const float*)d_in[8];
    const float* attb2   = (const float*)d_in[9];
    const float* attbias = (const float*)d_in[10];
    const float* relW    = (const float*)d_in[11];
    const float* relb    = (const float*)d_in[12];
    const float* gateW   = (const float*)d_in[13];
    const float* gateb   = (const float*)d_in[14];
    const float* vpref   = (const float*)d_in[15];
    const float* vattW1  = (const float*)d_in[16];
    const float* vattb1  = (const float*)d_in[17];
    const float* vattW2  = (const float*)d_in[18];
    const float* vattb2  = (const float*)d_in[19];
    const float* selfW   = (const float*)d_in[20];
    const float* selfb   = (const float*)d_in[21];
    const float* featW   = (const float*)d_in[22];
    const float* featb   = (const float*)d_in[23];
    const float* fusW    = (const float*)d_in[24];
    const float* fusb    = (const float*)d_in[25];
    const float* lng     = (const float*)d_in[26];
    const float* lnb     = (const float*)d_in[27];

    float* out = (float*)d_out;
    float* out_cp = out + (size_t)NN * 128;

    const int SMEM_FEAT = (8 + 16384 * 3) * 4;
    const int SMEM_VIEW = (8 + 16384 * 3 + 8192) * 4;
    const int SMEM_FUSE = (8 + 16384 * 3) * 4;

    cudaFuncSetAttribute(k_feat, cudaFuncAttributeMaxDynamicSharedMemorySize, SMEM_FEAT);
    cudaFuncSetAttribute(k_view, cudaFuncAttributeMaxDynamicSharedMemorySize, SMEM_VIEW);
    cudaFuncSetAttribute(k_fuse, cudaFuncAttributeMaxDynamicSharedMemorySize, SMEM_FUSE);

    // ---- fork branch B: pre, pre2 (-> eRG), feat (-> eFeat) ----
    cudaEventRecord(g_br.eFork, 0);
    cudaStreamWaitEvent(g_br.sB, g_br.eFork, 0);
    k_pre<<<128, 128, 0, g_br.sB>>>(selfW, selfb, fusW, fusb);
    {
        dim3 g2(128, VV);
        k_pre2<<<g2, 128, 0, g_br.sB>>>(relW, relb, gateW);
    }
    cudaEventRecord(g_br.eRG, g_br.sB);
    k_feat<<<NTILES, NT, SMEM_FEAT, g_br.sB>>>(feats, clsW, clsb, attW1, attb1, attW2, attb2,
                                               attbias, featW, featb, out_cp);
    cudaEventRecord(g_br.eFeat, g_br.sB);

    // ---- main stream: per-view zero + edge, each recording its event ----
    const int EDGE_BLOCKS = (int)(((long long)EE * 32 + 255) / 256);
    for (int v = 0; v < VV; ++v) {
        k_zero_v<<<1024, 256>>>(v);
        k_edge_v<<<EDGE_BLOCKS, 256>>>(v, esrc + (size_t)v * EE, edst + (size_t)v * EE,
                                       ew + (size_t)v * EE, feats);
        cudaEventRecord(g_br.eE[v], 0);
    }

    // ---- per-view k_view on its own stream, gated on (edge_v, RG) ----
    for (int v = 0; v < VV; ++v) {
        cudaStreamWaitEvent(g_br.sV[v], g_br.eE[v], 0);
        cudaStreamWaitEvent(g_br.sV[v], g_br.eRG, 0);
        k_view<<<NTILES, NT, SMEM_VIEW, g_br.sV[v]>>>(v, relW, relb, gateb, vpref,
                                                      vattW1, vattb1, vattW2, vattb2);
        cudaEventRecord(g_br.eV[v], g_br.sV[v]);
    }

    // ---- join: fuse needs all views + feat ----
    for (int v = 0; v < VV; ++v)
        cudaStreamWaitEvent(0, g_br.eV[v], 0);
    cudaStreamWaitEvent(0, g_br.eFeat, 0);

    k_fuse<<<NTILES, NT, SMEM_FUSE>>>(feats, fusW, lng, lnb, out);
}

// round 16
// speedup vs baseline: 1.4202x; 1.0022x over previous
#include <cuda_runtime.h>
#include <cstdint>

// ---------------- problem constants ----------------
#define NN 100000
#define VV 3
#define EE 500000
#define EPSL 1e-5f

#define BN 128         // nodes per tile
#define NT 512         // 16 warps; warp = 8-node row group
#define NTILES ((NN + BN - 1) / BN)   // 782

typedef unsigned long long ull;

// ---------------- scratch (device globals; no allocation) ----------------
__device__ float g_pre[(size_t)VV * NN * 128];
__device__ float g_wsum[VV * NN];
__device__ float g_transformed[(size_t)NN * 128];
__device__ float g_nodeatt[NN];
__device__ float g_viewout[(size_t)VV * NN * 128];
__device__ float g_vscore[VV * NN];
__device__ float g_W01[128 * 128];    // selfW @ fusW[0:128]
__device__ float g_b01[128];          // fusb + selfb @ fusW[0:128]
__device__ float g_RG[VV * 128 * 128];// relW[v] @ gateW[v]
__device__ float g_rbg[VV * 128];     // relb[v] @ gateW[v]
__device__ float g_fusA[(size_t)NN * 128];  // feats @ W01 (fuse phase A, precomputed on branch B)

// ---------------- streams/events for pipelined graph ----------------
struct BranchRes {
    cudaStream_t sB, sV[VV];
    cudaEvent_t eFork, eRG, eFeat, eE[VV], eV[VV];
    BranchRes() {
        cudaStreamCreateWithFlags(&sB, cudaStreamNonBlocking);
        cudaEventCreateWithFlags(&eFork, cudaEventDisableTiming);
        cudaEventCreateWithFlags(&eRG, cudaEventDisableTiming);
        cudaEventCreateWithFlags(&eFeat, cudaEventDisableTiming);
        for (int v = 0; v < VV; ++v) {
            cudaStreamCreateWithFlags(&sV[v], cudaStreamNonBlocking);
            cudaEventCreateWithFlags(&eE[v], cudaEventDisableTiming);
            cudaEventCreateWithFlags(&eV[v], cudaEventDisableTiming);
        }
    }
};
static BranchRes g_br;

// ---------------- small helpers ----------------
__device__ __forceinline__ void ffma2(ull &d, ull a, ull b) {
    asm("fma.rn.f32x2 %0, %1, %2, %0;" : "+l"(d) : "l"(a), "l"(b));
}
__device__ __forceinline__ ull fdup(float a) {
    ull r; asm("mov.b64 %0, {%1, %1};" : "=l"(r) : "f"(a)); return r;
}
__device__ __forceinline__ float2 u2f(ull v) {
    float2 r; asm("mov.b64 {%0, %1}, %2;" : "=f"(r.x), "=f"(r.y) : "l"(v)); return r;
}
__device__ __forceinline__ float sigm(float x) { return 1.f / (1.f + __expf(-x)); }

__device__ __forceinline__ unsigned smaddr(const void* p) {
    unsigned r;
    asm("{ .reg .u64 t; cvta.to.shared.u64 t, %1; cvt.u32.u64 %0, t; }" : "=r"(r) : "l"(p));
    return r;
}
#define MBAR_INIT(a) asm volatile("mbarrier.init.shared.b64 [%0], 1;" :: "r"(a))
#define MBAR_EXPECT(a, bytes) \
    asm volatile("mbarrier.arrive.expect_tx.shared.b64 _, [%0], %1;" :: "r"(a), "r"(bytes))
#define MBAR_WAIT(a, parity) do { \
    unsigned _p = 0; \
    while (!_p) { \
        asm volatile("{\n\t.reg .pred P;\n\t" \
                     "mbarrier.try_wait.parity.shared.b64 P, [%1], %2, 0x989680;\n\t" \
                     "selp.u32 %0, 1, 0, P;\n\t}" \
                     : "=r"(_p) : "r"(a), "r"((unsigned)(parity))); \
    } } while (0)

__device__ __forceinline__ void bulk_g2s(unsigned dst, const void* src, unsigned bytes, unsigned mbar) {
    asm volatile("cp.async.bulk.shared::cluster.global.mbarrier::complete_tx::bytes [%0], [%1], %2, [%3];"
                 :: "r"(dst), "l"(src), "r"(bytes), "r"(mbar) : "memory");
}

__device__ __forceinline__ float wred32(float x) {
#pragma unroll
    for (int off = 16; off > 0; off >>= 1)
        x += __shfl_xor_sync(0xffffffffu, x, off);
    return x;
}
__device__ __forceinline__ float wred16(float x) {
#pragma unroll
    for (int off = 8; off > 0; off >>= 1)
        x += __shfl_xor_sync(0xffffffffu, x, off);
    return x;
}

// ---------------- zero one view's scratch ----------------
__global__ void k_zero_v(int v) {
    size_t tid = (size_t)blockIdx.x * blockDim.x + threadIdx.x;
    size_t stride = (size_t)gridDim.x * blockDim.x;
    float4 z = make_float4(0.f, 0.f, 0.f, 0.f);
    float4* base = reinterpret_cast<float4*>(g_pre + (size_t)v * NN * 128);
    for (size_t i = tid; i < (size_t)NN * 32; i += stride)
        base[i] = z;
    for (size_t i = tid; i < NN; i += stride)
        g_wsum[(size_t)v * NN + i] = 0.f;
}

// ---------------- precompute W01 = selfW @ fusW[0:128), b01 ----------------
__global__ void k_pre(const float* __restrict__ selfW, const float* __restrict__ selfb,
                      const float* __restrict__ fusW, const float* __restrict__ fusb) {
    int c = threadIdx.x;
    int i = blockIdx.x;
    float s = 0.f;
#pragma unroll 8
    for (int m = 0; m < 128; ++m)
        s = fmaf(selfW[i * 128 + m], __ldg(fusW + m * 128 + c), s);
    g_W01[i * 128 + c] = s;
    if (i == 0) {
        float b = __ldg(fusb + c);
#pragma unroll 8
        for (int m = 0; m < 128; ++m)
            b = fmaf(__ldg(selfb + m), __ldg(fusW + m * 128 + c), b);
        g_b01[c] = b;
    }
}

// ---------------- precompute RG[v], rbg[v] ----------------
__global__ void k_pre2(const float* __restrict__ relW, const float* __restrict__ relb,
                       const float* __restrict__ gateW) {
    int c = threadIdx.x;
    int i = blockIdx.x;
    int v = blockIdx.y;
    const float* rw = relW + (size_t)v * 16384;
    const float* gw = gateW + (size_t)v * 16384;
    float s = 0.f;
#pragma unroll 8
    for (int m = 0; m < 128; ++m)
        s = fmaf(rw[i * 128 + m], __ldg(gw + m * 128 + c), s);
    g_RG[(size_t)v * 16384 + i * 128 + c] = s;
    if (i == 0) {
        float b = 0.f;
#pragma unroll 8
        for (int m = 0; m < 128; ++m)
            b = fmaf(__ldg(relb + v * 128 + m), __ldg(gw + m * 128 + c), b);
        g_rbg[v * 128 + c] = b;
    }
}

// ---------------- edge scatter for one view ----------------
__global__ void __launch_bounds__(256) k_edge_v(int v,
                                                const int* __restrict__ src,
                                                const int* __restrict__ dst,
                                                const float* __restrict__ w,
                                                const float* __restrict__ feats) {
    int gw = (int)(((size_t)blockIdx.x * 256 + threadIdx.x) >> 5);
    if (gw >= EE) return;
    int l = threadIdx.x & 31;
    int s = src[gw];
    int d = dst[gw];
    float we = w[gw];
    float4 x = reinterpret_cast<const float4*>(feats + (size_t)s * 128)[l];
    float* p = g_pre + ((size_t)v * NN + d) * 128 + l * 4;
    asm volatile("red.global.add.v4.f32 [%0], {%1,%2,%3,%4};" ::
                 "l"(p), "f"(we * x.x), "f"(we * x.y), "f"(we * x.z), "f"(we * x.w)
                 : "memory");
    if (l == 0) atomicAdd(&g_wsum[v * NN + d], we);
}

// ---------------- warp-private tile loader ----------------
__device__ __forceinline__ void load_rows_warp(const float* __restrict__ g, int nb, int n0,
                                               int lane, float* __restrict__ Fs) {
#pragma unroll
    for (int i = 0; i < 8; ++i) {
        int n = nb + n0 + i;
        float4 v = make_float4(0.f, 0.f, 0.f, 0.f);
        if (n < NN) v = reinterpret_cast<const float4*>(g + (size_t)n * 128)[lane];
        reinterpret_cast<float4*>(Fs + (n0 + i) * 128)[lane] = v;
    }
}

// ---------------- dual 8x4 matmul: two B matrices, shared A broadcast ----------------
template <int BS1, int BS2>
__device__ __forceinline__ void mm8x4_dual(const float* __restrict__ Fs,
                                           const float* __restrict__ w1,
                                           const float* __restrict__ w2,
                                           ull acc1[8][2], ull acc2[8][2], int n0) {
#pragma unroll 2
    for (int kk = 0; kk < 128; kk += 2) {
        float2 a2[8];
#pragma unroll
        for (int i = 0; i < 8; ++i)
            a2[i] = *reinterpret_cast<const float2*>(Fs + (n0 + i) * 128 + kk);
#pragma unroll
        for (int q = 0; q < 2; ++q) {
            ulonglong2 b1 = *reinterpret_cast<const ulonglong2*>(w1 + (kk + q) * BS1);
            ulonglong2 b2 = *reinterpret_cast<const ulonglong2*>(w2 + (kk + q) * BS2);
#pragma unroll
            for (int i = 0; i < 8; ++i) {
                ull ad = fdup(q ? a2[i].y : a2[i].x);
                ffma2(acc1[i][0], ad, b1.x);
                ffma2(acc1[i][1], ad, b1.y);
                ffma2(acc2[i][0], ad, b2.x);
                ffma2(acc2[i][1], ad, b2.y);
            }
        }
    }
}

// single 8x4
template <int BSTRIDE>
__device__ __forceinline__ void mm8x4(const float* __restrict__ Fs, const float* __restrict__ wbase,
                                      ull acc2[8][2], int n0) {
#pragma unroll 2
    for (int kk = 0; kk < 128; kk += 4) {
        float4 a4[8];
#pragma unroll
        for (int i = 0; i < 8; ++i)
            a4[i] = *reinterpret_cast<const float4*>(Fs + (n0 + i) * 128 + kk);
#pragma unroll
        for (int q = 0; q < 4; ++q) {
            ulonglong2 b = *reinterpret_cast<const ulonglong2*>(wbase + (kk + q) * BSTRIDE);
#pragma unroll
            for (int i = 0; i < 8; ++i) {
                float av = (q == 0) ? a4[i].x : (q == 1) ? a4[i].y : (q == 2) ? a4[i].z : a4[i].w;
                ull ad = fdup(av);
                ffma2(acc2[i][0], ad, b.x);
                ffma2(acc2[i][1], ad, b.y);
            }
        }
    }
}

__device__ __forceinline__ void mm8x2_64(const float* __restrict__ Fs, const float* __restrict__ wbase,
                                         ull acc[8], int n0) {
#pragma unroll 2
    for (int kk = 0; kk < 128; kk += 4) {
        float4 a4[8];
#pragma unroll
        for (int i = 0; i < 8; ++i)
            a4[i] = *reinterpret_cast<const float4*>(Fs + (n0 + i) * 128 + kk);
#pragma unroll
        for (int q = 0; q < 4; ++q) {
            ull b = *reinterpret_cast<const ull*>(wbase + (kk + q) * 64);
#pragma unroll
            for (int i = 0; i < 8; ++i) {
                float av = (q == 0) ? a4[i].x : (q == 1) ? a4[i].y : (q == 2) ? a4[i].z : a4[i].w;
                ffma2(acc[i], fdup(av), b);
            }
        }
    }
}

#define ZERO_ACC(acc2) do { \
    _Pragma("unroll") for (int i = 0; i < 8; ++i) { acc2[i][0] = 0ull; acc2[i][1] = 0ull; } } while (0)

// ---------------- feature-side kernel ----------------
// smem: [0:8) mbars | Fs 16384 | W0 16384 | W1 16384
__global__ void __launch_bounds__(NT, 1) k_feat(
    const float* __restrict__ feats,
    const float* __restrict__ clsW, const float* __restrict__ clsb,
    const float* __restrict__ attW1, const float* __restrict__ attb1,
    const float* __restrict__ attW2, const float* __restrict__ attb2,
    const float* __restrict__ attbias,
    const float* __restrict__ featW, const float* __restrict__ featb,
    float* __restrict__ out_cp) {
    extern __shared__ float sm[];
    float* Fs = sm + 8;
    float* W0 = Fs + 16384;
    float* W1 = W0 + 16384;
    unsigned mb0 = smaddr(sm), mb1 = mb0 + 8;

    int nb = blockIdx.x * BN;
    int t = threadIdx.x;
    int lane = t & 31;
    int ng = t >> 5;
    int n0 = ng * 8, c0 = lane * 4;

    if (t == 0) { MBAR_INIT(mb0); MBAR_INIT(mb1); }
    __syncthreads();
    if (t == 0) {
        MBAR_EXPECT(mb0, 65536u);
        bulk_g2s(smaddr(W0), featW, 65536u, mb0);
        MBAR_EXPECT(mb1, 65536u);
        bulk_g2s(smaddr(W1), attW1, 65536u, mb1);
    }
    load_rows_warp(feats, nb, n0, lane, Fs);
    __syncwarp();

    ull acc_t[8][2], acc_l[8][2];
    ZERO_ACC(acc_t);
    ZERO_ACC(acc_l);

    MBAR_WAIT(mb0, 0);
    MBAR_WAIT(mb1, 0);
    {
        int cls = c0 >> 6;
        mm8x4_dual<128, 64>(Fs, W0 + c0, W1 + cls * 8192 + (c0 & 63), acc_t, acc_l, n0);
    }

    {
        float4 b0 = __ldg(reinterpret_cast<const float4*>(featb + c0));
#pragma unroll
        for (int i = 0; i < 8; ++i) {
            int n = nb + n0 + i;
            if (n < NN) {
                float2 p0 = u2f(acc_t[i][0]), p1 = u2f(acc_t[i][1]);
                *reinterpret_cast<float4*>(g_transformed + (size_t)n * 128 + c0) =
                    make_float4(p0.x + b0.x, p0.y + b0.y, p1.x + b0.z, p1.y + b0.w);
            }
        }
    }

    float sc[8], sco[8];
    {
        int cls = c0 >> 6;
        float4 ab = __ldg(reinterpret_cast<const float4*>(attb1 + c0));
        float4 aw = __ldg(reinterpret_cast<const float4*>(attW2 + c0));
        float b2v = __ldg(attb2 + cls);
#pragma unroll
        for (int i = 0; i < 8; ++i) {
            float2 f0 = u2f(acc_l[i][0]), f1 = u2f(acc_l[i][1]);
            float p = fmaxf(f0.x + ab.x, 0.f) * aw.x
                    + fmaxf(f0.y + ab.y, 0.f) * aw.y
                    + fmaxf(f1.x + ab.z, 0.f) * aw.z
                    + fmaxf(f1.y + ab.w, 0.f) * aw.w;
            p = wred16(p);
            sc[i] = sigm(p + b2v);
            sco[i] = __shfl_xor_sync(0xffffffffu, sc[i], 16);
        }
    }

    {
        float4 cw0 = __ldg(reinterpret_cast<const float4*>(clsW + c0 * 2));
        float4 cw1 = __ldg(reinterpret_cast<const float4*>(clsW + c0 * 2) + 1);
        float cb0 = __ldg(clsb), cb1 = __ldg(clsb + 1), abv = __ldg(attbias);
#pragma unroll
        for (int i = 0; i < 8; ++i) {
            float4 f = *reinterpret_cast<const float4*>(Fs + (n0 + i) * 128 + c0);
            float p0 = f.x * cw0.x + f.y * cw0.z + f.z * cw1.x + f.w * cw1.z;
            float p1 = f.x * cw0.y + f.y * cw0.w + f.z * cw1.y + f.w * cw1.w;
            p0 = wred32(p0);
            p1 = wred32(p1);
            int n = nb + n0 + i;
            if (lane == 0 && n < NN) {
                float l0 = p0 + cb0, l1 = p1 + cb1;
                float m = fmaxf(l0, l1);
                float e0 = __expf(l0 - m), e1 = __expf(l1 - m);
                float inv = 1.f / (e0 + e1);
                float cp0 = e0 * inv, cp1 = e1 * inv;
                out_cp[(size_t)n * 2] = cp0;
                out_cp[(size_t)n * 2 + 1] = cp1;
                g_nodeatt[n] = sc[i] * cp0 + sco[i] * cp1 + abv;
            }
        }
    }
}

// ---------------- fuse phase A: g_fusA = feats @ W01 (runs hidden on branch B) ----------------
// smem: [0:8) mbars | Fs 16384 | W0 16384
__global__ void __launch_bounds__(NT, 1) k_fuseA(const float* __restrict__ feats) {
    extern __shared__ float sm[];
    float* Fs = sm + 8;
    float* W0 = Fs + 16384;
    unsigned mb0 = smaddr(sm);

    int nb = blockIdx.x * BN;
    int t = threadIdx.x;
    int lane = t & 31;
    int ng = t >> 5;
    int n0 = ng * 8, c0 = lane * 4;

    if (t == 0) MBAR_INIT(mb0);
    __syncthreads();
    if (t == 0) {
        MBAR_EXPECT(mb0, 65536u);
        bulk_g2s(smaddr(W0), g_W01, 65536u, mb0);
    }
    load_rows_warp(feats, nb, n0, lane, Fs);
    __syncwarp();

    ull acc2[8][2];
    MBAR_WAIT(mb0, 0);
    ZERO_ACC(acc2);
    mm8x4<128>(Fs, W0 + c0, acc2, n0);
#pragma unroll
    for (int i = 0; i < 8; ++i) {
        int n = nb + n0 + i;
        if (n < NN) {
            float2 p0 = u2f(acc2[i][0]), p1 = u2f(acc2[i][1]);
            *reinterpret_cast<float4*>(g_fusA + (size_t)n * 128 + c0) =
                make_float4(p0.x, p0.y, p1.x, p1.y);
        }
    }
}

// ---------------- per-view kernel (unchanged from R13) ----------------
// smem: [0:8) mbars | Fs 16384 | W0 16384 | W1 16384 | W2 8192
__global__ void __launch_bounds__(NT, 1) k_view(
    int v,
    const float* __restrict__ relW, const float* __restrict__ relb,
    const float* __restrict__ gateb,
    const float* __restrict__ view_pref,
    const float* __restrict__ vattW1, const float* __restrict__ vattb1,
    const float* __restrict__ vattW2, const float* __restrict__ vattb2) {
    extern __shared__ float sm[];
    float* Fs = sm + 8;
    float* W0 = Fs + 16384;
    float* W1 = W0 + 16384;
    float* W2 = W1 + 16384;
    unsigned mb0 = smaddr(sm), mb1 = mb0 + 8, mb2 = mb0 + 16;

    int nb = blockIdx.x * BN;
    int t = threadIdx.x;
    int lane = t & 31;
    int ng = t >> 5;
    int n0 = ng * 8, c0 = lane * 4;

    if (t == 0) { MBAR_INIT(mb0); MBAR_INIT(mb1); MBAR_INIT(mb2); }
    __syncthreads();
    if (t == 0) {
        MBAR_EXPECT(mb0, 65536u);
        bulk_g2s(smaddr(W0), relW + (size_t)v * 16384, 65536u, mb0);
        MBAR_EXPECT(mb1, 65536u);
        bulk_g2s(smaddr(W1), g_RG + (size_t)v * 16384, 65536u, mb1);
        MBAR_EXPECT(mb2, 32768u);
        bulk_g2s(smaddr(W2), vattW1, 32768u, mb2);
    }
    load_rows_warp(g_pre + (size_t)v * NN * 128, nb, n0, lane, Fs);
    float ws_r = 0.f;
    if (lane < 8) {
        int n = nb + n0 + lane;
        if (n < NN) ws_r = __ldg(g_wsum + v * NN + n);
    }
    __syncwarp();

    ull acc_a[8][2], acc_g[8][2];
    ZERO_ACC(acc_a);
    ZERO_ACC(acc_g);
    MBAR_WAIT(mb0, 0);
    MBAR_WAIT(mb1, 0);
    mm8x4_dual<128, 128>(Fs, W0 + c0, W1 + c0, acc_a, acc_g, n0);
    {
        ulonglong2 r01 = __ldg(reinterpret_cast<const ulonglong2*>(relb + v * 128 + c0));
        ulonglong2 q01 = __ldg(reinterpret_cast<const ulonglong2*>(g_rbg + v * 128 + c0));
#pragma unroll
        for (int i = 0; i < 8; ++i) {
            ull wd = fdup(__shfl_sync(0xffffffffu, ws_r, i));
            ffma2(acc_a[i][0], wd, r01.x);
            ffma2(acc_a[i][1], wd, r01.y);
            ffma2(acc_g[i][0], wd, q01.x);
            ffma2(acc_g[i][1], wd, q01.y);
        }
    }

    {
        float4 gb = __ldg(reinterpret_cast<const float4*>(gateb + v * 128 + c0));
        float4 vp = __ldg(reinterpret_cast<const float4*>(view_pref + v * 128 + c0));
#pragma unroll
        for (int i = 0; i < 8; ++i) {
            int n = nb + n0 + i;
            float2 g0 = u2f(acc_g[i][0]), g1 = u2f(acc_g[i][1]);
            float2 a0 = u2f(acc_a[i][0]), a1 = u2f(acc_a[i][1]);
            float vo0 = sigm(g0.x + gb.x) * a0.x;
            float vo1 = sigm(g0.y + gb.y) * a0.y;
            float vo2 = sigm(g1.x + gb.z) * a1.x;
            float vo3 = sigm(g1.y + gb.w) * a1.y;
            if (n < NN)
                *reinterpret_cast<float4*>(g_viewout + ((size_t)v * NN + n) * 128 + c0) =
                    make_float4(vo0, vo1, vo2, vo3);
            *reinterpret_cast<float4*>(Fs + (n0 + i) * 128 + c0) =
                make_float4(vo0 * vp.x, vo1 * vp.y, vo2 * vp.z, vo3 * vp.w);
        }
    }
    __syncwarp();

    ull vac[8];
    MBAR_WAIT(mb2, 0);
#pragma unroll
    for (int i = 0; i < 8; ++i) vac[i] = 0ull;
    mm8x2_64(Fs, W2 + lane * 2, vac, n0);
    {
        int cv = lane * 2;
        float2 vb = __ldg(reinterpret_cast<const float2*>(vattb1 + cv));
        float2 vw = __ldg(reinterpret_cast<const float2*>(vattW2 + cv));
        float b2v = __ldg(vattb2);
#pragma unroll
        for (int i = 0; i < 8; ++i) {
            float2 f0 = u2f(vac[i]);
            float s = fmaxf(f0.x + vb.x, 0.f) * vw.x + fmaxf(f0.y + vb.y, 0.f) * vw.y;
            s = wred32(s);
            int n = nb + n0 + i;
            if (lane == 0 && n < NN) g_vscore[v * NN + n] = s + b2v;
        }
    }
}

// ---------------- fuse phase B: weighted GEMM + residual + layer norm ----------------
// smem: [0:8) mbars | Zs 16384 | W1 16384
__global__ void __launch_bounds__(NT, 1) k_fuseB(
    const float* __restrict__ fusW,
    const float* __restrict__ ln_g, const float* __restrict__ ln_b,
    float* __restrict__ out) {
    extern __shared__ float sm[];
    float* Zs = sm + 8;
    float* W1 = Zs + 16384;
    unsigned mb1 = smaddr(sm);

    int nb = blockIdx.x * BN;
    int t = threadIdx.x;
    int lane = t & 31;
    int ng = t >> 5;
    int n0 = ng * 8, c0 = lane * 4;

    if (t == 0) MBAR_INIT(mb1);
    __syncthreads();
    if (t == 0) {
        MBAR_EXPECT(mb1, 65536u);
        bulk_g2s(smaddr(W1), fusW + 16384, 65536u, mb1);
    }
    float vw0_r = 0.f, vw1_r = 0.f, vw2_r = 0.f;
    if (lane < 8) {
        int n = nb + n0 + lane;
        float s0 = 0.f, s1 = 0.f, s2 = 0.f, na = 0.f;
        if (n < NN) {
            s0 = __ldg(g_vscore + n);
            s1 = __ldg(g_vscore + NN + n);
            s2 = __ldg(g_vscore + 2 * NN + n);
            na = __ldg(g_nodeatt + n);
        }
        float m = fmaxf(s0, fmaxf(s1, s2));
        float e0 = __expf(s0 - m), e1 = __expf(s1 - m), e2 = __expf(s2 - m);
        float inv = na / (e0 + e1 + e2);
        vw0_r = e0 * inv; vw1_r = e1 * inv; vw2_r = e2 * inv;
    }

    // build weighted view-combo tile (warp-private rows)
#pragma unroll
    for (int i = 0; i < 8; ++i) {
        int nl = n0 + i;
        int n = nb + nl;
        float w0 = __shfl_sync(0xffffffffu, vw0_r, i);
        float w1 = __shfl_sync(0xffffffffu, vw1_r, i);
        float w2 = __shfl_sync(0xffffffffu, vw2_r, i);
        float4 a = make_float4(0.f, 0.f, 0.f, 0.f);
        if (n < NN) {
            float4 x0 = reinterpret_cast<const float4*>(g_viewout + (size_t)n * 128)[lane];
            float4 x1 = reinterpret_cast<const float4*>(g_viewout + ((size_t)NN + n) * 128)[lane];
            float4 x2 = reinterpret_cast<const float4*>(g_viewout + ((size_t)2 * NN + n) * 128)[lane];
            a.x = w0 * x0.x + w1 * x1.x + w2 * x2.x;
            a.y = w0 * x0.y + w1 * x1.y + w2 * x2.y;
            a.z = w0 * x0.z + w1 * x1.z + w2 * x2.z;
            a.w = w0 * x0.w + w1 * x1.w + w2 * x2.w;
        }
        reinterpret_cast<float4*>(Zs + nl * 128)[lane] = a;
    }
    __syncwarp();

    ull acc2[8][2];
    MBAR_WAIT(mb1, 0);
    ZERO_ACC(acc2);
    mm8x4<128>(Zs, W1 + c0, acc2, n0);

    // epilogue: f = relu(fusA + acc + b01) + transformed, LN via warp reduce
    {
        float4 fb = __ldg(reinterpret_cast<const float4*>(g_b01 + c0));
        float4 lg = __ldg(reinterpret_cast<const float4*>(ln_g + c0));
        float4 lb = __ldg(reinterpret_cast<const float4*>(ln_b + c0));
#pragma unroll
        for (int i = 0; i < 8; ++i) {
            int n = nb + n0 + i;
            if (n >= NN) continue;   // uniform across warp
            float4 la = *reinterpret_cast<const float4*>(g_fusA + (size_t)n * 128 + c0);
            float4 tr = *reinterpret_cast<const float4*>(g_transformed + (size_t)n * 128 + c0);
            float2 l0 = u2f(acc2[i][0]), l1 = u2f(acc2[i][1]);
            float f0 = fmaxf(la.x + l0.x + fb.x, 0.f) + tr.x;
            float f1 = fmaxf(la.y + l0.y + fb.y, 0.f) + tr.y;
            float f2 = fmaxf(la.z + l1.x + fb.z, 0.f) + tr.z;
            float f3 = fmaxf(la.w + l1.y + fb.w, 0.f) + tr.w;
            float s = f0 + f1 + f2 + f3;
            float s2 = f0 * f0 + f1 * f1 + f2 * f2 + f3 * f3;
            s = wred32(s);
            s2 = wred32(s2);
            float mu = s * (1.f / 128.f);
            float var = s2 * (1.f / 128.f) - mu * mu;
            float rs = rsqrtf(var + EPSL);
            *reinterpret_cast<float4*>(out + (size_t)n * 128 + c0) =
                make_float4((f0 - mu) * rs * lg.x + lb.x,
                            (f1 - mu) * rs * lg.y + lb.y,
                            (f2 - mu) * rs * lg.z + lb.z,
                            (f3 - mu) * rs * lg.w + lb.w);
        }
    }
}

// ---------------- launch ----------------
extern "C" void kernel_launch(void* const* d_in, const int* in_sizes, int n_in,
                              void* d_out, int out_size) {
    const float* feats   = (const float*)d_in[0];
    const int*   esrc    = (const int*)d_in[1];
    const int*   edst    = (const int*)d_in[2];
    const float* ew      = (const float*)d_in[3];
    const float* clsW    = (const float*)d_in[4];
    const float* clsb    = (const float*)d_in[5];
    const float* attW1   = (const float*)d_in[6];
    const float* attb1   = (const float*)d_in[7];
    const float* attW2   = (const float*)d_in[8];
    const float* attb2   = (const float*)d_in[9];
    const float* attbias = (const float*)d_in[10];
    const float* relW    = (const float*)d_in[11];
    const float* relb    = (const float*)d_in[12];
    const float* gateW   = (const float*)d_in[13];
    const float* gateb   = (const float*)d_in[14];
    const float* vpref   = (const float*)d_in[15];
    const float* vattW1  = (const float*)d_in[16];
    const float* vattb1  = (const float*)d_in[17];
    const float* vattW2  = (const float*)d_in[18];
    const float* vattb2  = (const float*)d_in[19];
    const float* selfW   = (const float*)d_in[20];
    const float* selfb   = (const float*)d_in[21];
    const float* featW   = (const float*)d_in[22];
    const float* featb   = (const float*)d_in[23];
    const float* fusW    = (const float*)d_in[24];
    const float* fusb    = (const float*)d_in[25];
    const float* lng     = (const float*)d_in[26];
    const float* lnb     = (const float*)d_in[27];

    float* out = (float*)d_out;
    float* out_cp = out + (size_t)NN * 128;

    const int SMEM_FEAT  = (8 + 16384 * 3) * 4;
    const int SMEM_FUSEA = (8 + 16384 * 2) * 4;
    const int SMEM_VIEW  = (8 + 16384 * 3 + 8192) * 4;
    const int SMEM_FUSEB = (8 + 16384 * 2) * 4;

    cudaFuncSetAttribute(k_feat, cudaFuncAttributeMaxDynamicSharedMemorySize, SMEM_FEAT);
    cudaFuncSetAttribute(k_fuseA, cudaFuncAttributeMaxDynamicSharedMemorySize, SMEM_FUSEA);
    cudaFuncSetAttribute(k_view, cudaFuncAttributeMaxDynamicSharedMemorySize, SMEM_VIEW);
    cudaFuncSetAttribute(k_fuseB, cudaFuncAttributeMaxDynamicSharedMemorySize, SMEM_FUSEB);

    // ---- fork branch B: pre, pre2 (-> eRG), feat, fuseA (-> eFeat) ----
    cudaEventRecord(g_br.eFork, 0);
    cudaStreamWaitEvent(g_br.sB, g_br.eFork, 0);
    k_pre<<<128, 128, 0, g_br.sB>>>(selfW, selfb, fusW, fusb);
    {
        dim3 g2(128, VV);
        k_pre2<<<g2, 128, 0, g_br.sB>>>(relW, relb, gateW);
    }
    cudaEventRecord(g_br.eRG, g_br.sB);
    k_feat<<<NTILES, NT, SMEM_FEAT, g_br.sB>>>(feats, clsW, clsb, attW1, attb1, attW2, attb2,
                                               attbias, featW, featb, out_cp);
    k_fuseA<<<NTILES, NT, SMEM_FUSEA, g_br.sB>>>(feats);
    cudaEventRecord(g_br.eFeat, g_br.sB);

    // ---- main stream: per-view zero + edge ----
    const int EDGE_BLOCKS = (int)(((long long)EE * 32 + 255) / 256);
    for (int v = 0; v < VV; ++v) {
        k_zero_v<<<1024, 256>>>(v);
        k_edge_v<<<EDGE_BLOCKS, 256>>>(v, esrc + (size_t)v * EE, edst + (size_t)v * EE,
                                       ew + (size_t)v * EE, feats);
        cudaEventRecord(g_br.eE[v], 0);
    }

    // ---- per-view k_view gated on (edge_v, RG) ----
    for (int v = 0; v < VV; ++v) {
        cudaStreamWaitEvent(g_br.sV[v], g_br.eE[v], 0);
        cudaStreamWaitEvent(g_br.sV[v], g_br.eRG, 0);
        k_view<<<NTILES, NT, SMEM_VIEW, g_br.sV[v]>>>(v, relW, relb, gateb, vpref,
                                                      vattW1, vattb1, vattW2, vattb2);
        cudaEventRecord(g_br.eV[v], g_br.sV[v]);
    }

    // ---- join: fuseB needs all views + feat + fuseA ----
    for (int v = 0; v < VV; ++v)
        cudaStreamWaitEvent(0, g_br.eV[v], 0);
    cudaStreamWaitEvent(0, g_br.eFeat, 0);

    k_fuseB<<<NTILES, NT, SMEM_FUSEB>>>(fusW, lng, lnb, out);
}